// round 10
// baseline (speedup 1.0000x reference)
#include <cuda_runtime.h>
#include <cuda_bf16.h>
#include <cuda_fp16.h>
#include <cstdint>

// ---------------- Problem constants (fixed by the dataset) ----------------
#define D_MODEL   256
#define N_HEADS   8
#define HEAD_DIM  32
#define N_LEVELS  4
#define N_POINTS  4
#define LEN_IN    22223
#define NBATCH    2
#define TOTQ      (NBATCH * LEN_IN)   // 44446

__device__ __constant__ int   c_W[4] = {167, 84, 42, 21};
__device__ __constant__ int   c_H[4] = {100, 50, 25, 13};
__device__ __constant__ int   c_ST[4] = {0, 16700, 20900, 21950};

// ---------------- Scratch (device globals; no allocation allowed) ---------
__device__ __half g_value[(size_t)TOTQ * 256];   // fp16 value (written by GEMM)
__device__ float  g_off  [(size_t)TOTQ * 256];
__device__ float  g_attn [(size_t)TOTQ * 128];
__device__ __nv_bfloat16 g_hhi[(size_t)TOTQ * 256];  // sampled head output, split
__device__ __nv_bfloat16 g_hlo[(size_t)TOTQ * 256];
// split-bf16 weights, [n][k] row-major (k contiguous, 256 per row)
// [0,65536)=w_value  [65536,131072)=w_off  [131072,163840)=w_attn  [163840,229376)=w_out
__device__ __nv_bfloat16 g_bhi[229376];
__device__ __nv_bfloat16 g_blo[229376];

// ---------------- helpers ---------------------------------------------------
__device__ __forceinline__ uint32_t smem_u32(const void* p) {
    uint32_t a;
    asm("{ .reg .u64 t; cvta.to.shared.u64 t, %1; cvt.u32.u64 %0, t; }" : "=r"(a) : "l"(p));
    return a;
}
__device__ __forceinline__ void split2(float a, float b, uint32_t& hi, uint32_t& lo) {
    const __nv_bfloat16 ha = __float2bfloat16(a);
    const __nv_bfloat16 hb = __float2bfloat16(b);
    hi = ((uint32_t)__bfloat16_as_ushort(hb) << 16) | __bfloat16_as_ushort(ha);
    const __nv_bfloat16 la = __float2bfloat16(a - __bfloat162float(ha));
    const __nv_bfloat16 lb = __float2bfloat16(b - __bfloat162float(hb));
    lo = ((uint32_t)__bfloat16_as_ushort(lb) << 16) | __bfloat16_as_ushort(la);
}
__device__ __forceinline__ void ldm_x4(uint32_t* r, uint32_t addr) {
    asm volatile("ldmatrix.sync.aligned.m8n8.x4.shared.b16 {%0,%1,%2,%3}, [%4];"
                 : "=r"(r[0]), "=r"(r[1]), "=r"(r[2]), "=r"(r[3]) : "r"(addr));
}
__device__ __forceinline__ void mma_bf16(float* d, const uint32_t* a, uint32_t b0, uint32_t b1) {
    asm volatile(
        "mma.sync.aligned.m16n8k16.row.col.f32.bf16.bf16.f32 "
        "{%0,%1,%2,%3}, {%4,%5,%6,%7}, {%8,%9}, {%0,%1,%2,%3};"
        : "+f"(d[0]), "+f"(d[1]), "+f"(d[2]), "+f"(d[3])
        : "r"(a[0]), "r"(a[1]), "r"(a[2]), "r"(a[3]), "r"(b0), "r"(b1));
}
__device__ __forceinline__ void cp16(uint32_t dst, const void* src) {
    asm volatile("cp.async.cg.shared.global [%0], [%1], 16;" :: "r"(dst), "l"(src) : "memory");
}
#define CP_COMMIT() asm volatile("cp.async.commit_group;" ::: "memory")
#define CP_WAIT0()  asm volatile("cp.async.wait_group 0;" ::: "memory")

// ---------------- Weight prep: transpose + bf16 hi/lo split ----------------
__global__ void prep_weights(const float* __restrict__ wv, const float* __restrict__ wo,
                             const float* __restrict__ wa, const float* __restrict__ wu)
{
    const int idx = blockIdx.x * 256 + threadIdx.x;
    if (idx >= 229376) return;
    float a;
    if (idx < 65536)       { int l = idx;          int n = l >> 8, k = l & 255; a = wv[k * 256 + n]; }
    else if (idx < 131072) { int l = idx - 65536;  int n = l >> 8, k = l & 255; a = wo[k * 256 + n]; }
    else if (idx < 163840) { int l = idx - 131072; int n = l >> 8, k = l & 255; a = wa[k * 128 + n]; }
    else                   { int l = idx - 163840; int n = l >> 8, k = l & 255; a = wu[k * 256 + n]; }
    const __nv_bfloat16 h = __float2bfloat16(a);
    g_bhi[idx] = h;
    g_blo[idx] = __float2bfloat16(a - __bfloat162float(h));
}

// ---------------- GEMM tiles ------------------------------------------------
// 128x64 CTA tile, BK=32, 8 warps (4m x 2n), warp tile 32x32, m16n8k16.
// 3-pass split bf16 (hh + lh + hl).
#define SROW 80               // smem row stride (bytes): 32 bf16 + pad
#define AREG (128 * SROW)     // 10240
#define BREG (64 * SROW)      // 5120
#define BUFB (2 * AREG + 2 * BREG)   // 30720 per buffer: Ah, Al, Bh, Bl

// ---- compute core shared by both GEMM kernels ----
struct GemmCtx {
    uint32_t sbase;
    int warp_m, warp_n, lane;
    uint32_t blane;
    float acc[2][4][4];
};

__device__ __forceinline__ void compute_chunk(GemmCtx& g, int b) {
    const uint32_t aAh = g.sbase + b * BUFB;
    const uint32_t aAl = aAh + AREG;
    const uint32_t aBh = aAh + 2 * AREG;
    const uint32_t aBl = aBh + BREG;
    #pragma unroll
    for (int ks = 0; ks < 2; ks++) {
        uint32_t ah[2][4], al[2][4];
        #pragma unroll
        for (int ma = 0; ma < 2; ma++) {
            const uint32_t ao = (uint32_t)((g.warp_m * 32 + ma * 16 + (g.lane & 15)) * SROW
                                           + ks * 32 + (g.lane >> 4) * 16);
            ldm_x4(ah[ma], aAh + ao);
            ldm_x4(al[ma], aAl + ao);
        }
        #pragma unroll
        for (int np = 0; np < 2; np++) {
            const uint32_t bo = g.blane + (uint32_t)((g.warp_n * 32 + np * 16) * SROW + ks * 32);
            uint32_t bh[4], bl[4];
            ldm_x4(bh, aBh + bo);
            ldm_x4(bl, aBl + bo);
            #pragma unroll
            for (int h = 0; h < 2; h++) {
                const int na = np * 2 + h;
                #pragma unroll
                for (int ma = 0; ma < 2; ma++) {
                    mma_bf16(g.acc[ma][na], ah[ma], bh[2 * h], bh[2 * h + 1]);
                    mma_bf16(g.acc[ma][na], al[ma], bh[2 * h], bh[2 * h + 1]);
                    mma_bf16(g.acc[ma][na], ah[ma], bl[2 * h], bl[2 * h + 1]);
                }
            }
        }
    }
}

template<typename OutT>
__device__ __forceinline__ void epilogue(GemmCtx& g, const float* bias, OutT* C,
                                         int M, int N, int bm, int bn) {
    #pragma unroll
    for (int ma = 0; ma < 2; ma++) {
        const int row0 = bm + g.warp_m * 32 + ma * 16 + (g.lane >> 2);
        const int row1 = row0 + 8;
        #pragma unroll
        for (int na = 0; na < 4; na++) {
            const int col = bn + g.warp_n * 32 + na * 8 + 2 * (g.lane & 3);
            const float2 bv = *reinterpret_cast<const float2*>(bias + col);
            if constexpr (sizeof(OutT) == 2) {
                if (row0 < M) {
                    __half2 o = __floats2half2_rn(g.acc[ma][na][0] + bv.x, g.acc[ma][na][1] + bv.y);
                    *reinterpret_cast<__half2*>(&C[(size_t)row0 * N + col]) = o;
                }
                if (row1 < M) {
                    __half2 o = __floats2half2_rn(g.acc[ma][na][2] + bv.x, g.acc[ma][na][3] + bv.y);
                    *reinterpret_cast<__half2*>(&C[(size_t)row1 * N + col]) = o;
                }
            } else {
                if (row0 < M) {
                    float2 o = make_float2(g.acc[ma][na][0] + bv.x, g.acc[ma][na][1] + bv.y);
                    *reinterpret_cast<float2*>(&C[(size_t)row0 * N + col]) = o;
                }
                if (row1 < M) {
                    float2 o = make_float2(g.acc[ma][na][2] + bv.x, g.acc[ma][na][3] + bv.y);
                    *reinterpret_cast<float2*>(&C[(size_t)row1 * N + col]) = o;
                }
            }
        }
    }
}

__device__ __forceinline__ void ctx_init(GemmCtx& g, const void* smem, int tid) {
    g.sbase = smem_u32(smem);
    const int wid = tid >> 5;
    g.lane = tid & 31;
    g.warp_m = wid & 3;
    g.warp_n = wid >> 2;
    g.blane = (uint32_t)(((g.lane & 7) + ((g.lane >> 4) << 3)) * SROW
                         + ((g.lane >> 3) & 1) * 16);
    #pragma unroll
    for (int i = 0; i < 2; i++)
        #pragma unroll
        for (int j = 0; j < 4; j++)
            #pragma unroll
            for (int k = 0; k < 4; k++) g.acc[i][j][k] = 0.f;
}

// ---- front GEMM: A fp32 (split in-kernel), B pre-split -----
template<typename OutT>
__device__ __forceinline__ void gemm_f32A(
    const float* __restrict__ A,
    const __nv_bfloat16* __restrict__ Bhi,
    const __nv_bfloat16* __restrict__ Blo,
    const float* __restrict__ bias,
    OutT* __restrict__ C,
    int M, int N, int bm, int bn)
{
    extern __shared__ uint8_t dyns[];
    const int tid = threadIdx.x;
    GemmCtx g;
    ctx_init(g, dyns, tid);

    const int arow  = tid >> 1;
    const int akseg = (tid & 1) * 16;
    const int gr    = bm + arow;
    const int bnr   = tid >> 2;     // 0..63
    const int bseg  = tid & 3;

    float4 f[4];

    auto issue_B = [&](int c, int b) {
        const int k0 = c * 32;
        const uint32_t dBh = g.sbase + b * BUFB + 2 * AREG;
        const size_t go = (size_t)(bn + bnr) * 256 + k0 + bseg * 8;
        const uint32_t o = bnr * SROW + bseg * 16;
        cp16(dBh + o, Bhi + go);
        cp16(dBh + BREG + o, Blo + go);
        CP_COMMIT();
    };
    auto load_A = [&](int c) {
        const int k0 = c * 32;
        if (gr < M) {
            const float4* s = reinterpret_cast<const float4*>(A + (size_t)gr * 256 + k0 + akseg);
            f[0] = s[0]; f[1] = s[1]; f[2] = s[2]; f[3] = s[3];
        } else {
            f[0] = f[1] = f[2] = f[3] = make_float4(0.f, 0.f, 0.f, 0.f);
        }
    };
    auto store_A = [&](int b) {
        uint8_t* sAh = dyns + b * BUFB;
        uint8_t* sAl = sAh + AREG;
        uint32_t hp[8], lp[8];
        split2(f[0].x, f[0].y, hp[0], lp[0]);
        split2(f[0].z, f[0].w, hp[1], lp[1]);
        split2(f[1].x, f[1].y, hp[2], lp[2]);
        split2(f[1].z, f[1].w, hp[3], lp[3]);
        split2(f[2].x, f[2].y, hp[4], lp[4]);
        split2(f[2].z, f[2].w, hp[5], lp[5]);
        split2(f[3].x, f[3].y, hp[6], lp[6]);
        split2(f[3].z, f[3].w, hp[7], lp[7]);
        const int aoff = arow * SROW + akseg * 2;
        *reinterpret_cast<uint4*>(sAh + aoff)      = make_uint4(hp[0], hp[1], hp[2], hp[3]);
        *reinterpret_cast<uint4*>(sAh + aoff + 16) = make_uint4(hp[4], hp[5], hp[6], hp[7]);
        *reinterpret_cast<uint4*>(sAl + aoff)      = make_uint4(lp[0], lp[1], lp[2], lp[3]);
        *reinterpret_cast<uint4*>(sAl + aoff + 16) = make_uint4(lp[4], lp[5], lp[6], lp[7]);
    };

    issue_B(0, 0);
    load_A(0);
    store_A(0);
    CP_WAIT0();
    __syncthreads();

    #pragma unroll 1
    for (int c = 0; c < 8; c++) {
        const int b = c & 1;
        if (c < 7) {
            issue_B(c + 1, b ^ 1);
            load_A(c + 1);
        }
        compute_chunk(g, b);
        if (c < 7) {
            store_A(b ^ 1);
            CP_WAIT0();
            __syncthreads();
        }
    }
    epilogue(g, bias, C, M, N, bm, bn);
}

// ---- final GEMM: A pre-split bf16 (cp.async), B pre-split -----
__device__ __forceinline__ void gemm_splitA(
    const __nv_bfloat16* __restrict__ Ahi,
    const __nv_bfloat16* __restrict__ Alo,
    const __nv_bfloat16* __restrict__ Bhi,
    const __nv_bfloat16* __restrict__ Blo,
    const float* __restrict__ bias,
    float* __restrict__ C,
    int M, int N, int bm, int bn)
{
    extern __shared__ uint8_t dyns[];
    const int tid = threadIdx.x;
    GemmCtx g;
    ctx_init(g, dyns, tid);

    const int bnr  = tid >> 2;
    const int bseg = tid & 3;

    auto issue_chunk = [&](int c, int b) {
        const int k0 = c * 32;
        const uint32_t dAh = g.sbase + b * BUFB;
        const uint32_t dAl = dAh + AREG;
        const uint32_t dBh = dAh + 2 * AREG;
        // A: 512 x 16B per region; 2 per thread per region
        #pragma unroll
        for (int i = 0; i < 2; i++) {
            const int idx = i * 256 + tid;
            const int row = idx >> 2;
            const int seg = idx & 3;
            const uint32_t so = row * SROW + seg * 16;
            if (bm + row < M) {
                const size_t go = (size_t)(bm + row) * 256 + k0 + seg * 8;
                cp16(dAh + so, Ahi + go);
                cp16(dAl + so, Alo + go);
            }
        }
        // B: 256 x 16B per region; 1 per thread per region
        const size_t go = (size_t)(bn + bnr) * 256 + k0 + bseg * 8;
        const uint32_t o = bnr * SROW + bseg * 16;
        cp16(dBh + o, Bhi + go);
        cp16(dBh + BREG + o, Blo + go);
        CP_COMMIT();
    };

    issue_chunk(0, 0);
    CP_WAIT0();
    __syncthreads();

    #pragma unroll 1
    for (int c = 0; c < 8; c++) {
        const int b = c & 1;
        if (c < 7) issue_chunk(c + 1, b ^ 1);
        compute_chunk(g, b);
        if (c < 7) {
            CP_WAIT0();
            __syncthreads();
        }
    }
    epilogue(g, bias, C, M, N, bm, bn);
}

// Fused front GEMMs: grid.x = 10  (0-3: value->fp16 | 4-7: offsets | 8-9: attn)
__global__ __launch_bounds__(256, 3)
void front_gemm(const float* __restrict__ query,
                const float* __restrict__ inflat,
                const float* __restrict__ b_value,
                const float* __restrict__ b_off,
                const float* __restrict__ b_attn,
                int M)
{
    const int bx = blockIdx.x;
    const int bm = blockIdx.y * 128;
    if (bx < 4) {
        gemm_f32A<__half>(inflat, g_bhi, g_blo, b_value, g_value, M, 256, bm, bx * 64);
    } else if (bx < 8) {
        gemm_f32A<float>(query, g_bhi + 65536, g_blo + 65536, b_off, g_off, M, 256, bm, (bx - 4) * 64);
    } else {
        gemm_f32A<float>(query, g_bhi + 131072, g_blo + 131072, b_attn, g_attn, M, 128, bm, (bx - 8) * 64);
    }
}

// Final GEMM: out = head @ w_out + b_out   (A pre-split by sampling kernel)
__global__ __launch_bounds__(256, 3)
void final_gemm(const float* __restrict__ b_out, float* __restrict__ out, int M)
{
    gemm_splitA(g_hhi, g_hlo, g_bhi + 163840, g_blo + 163840, b_out, out,
                M, 256, blockIdx.y * 128, blockIdx.x * 64);
}

// ---------------- Sampling kernel -----------------------------------------
// One warp per query. lane = head*4 + quad; each lane handles 8 fp16 channels.
// Writes g_hhi/g_hlo (bf16 split) for the final GEMM.
__device__ __forceinline__ void acc8(float* a, const uint4& v, float w) {
    const __half2* h = reinterpret_cast<const __half2*>(&v);
    #pragma unroll
    for (int i = 0; i < 4; i++) {
        const float2 f = __half22float2(h[i]);
        a[2 * i]     = fmaf(f.x, w, a[2 * i]);
        a[2 * i + 1] = fmaf(f.y, w, a[2 * i + 1]);
    }
}

__global__ __launch_bounds__(256)
void msda_sample(const float* __restrict__ ref)
{
    const int q = blockIdx.x * 8 + (threadIdx.x >> 5);
    if (q >= TOTQ) return;
    const int lane = threadIdx.x & 31;
    const int m = lane >> 2;        // head 0..7
    const int j = lane & 3;         // quad 0..3 (8 channels)
    const int n = (q >= LEN_IN) ? 1 : 0;

    const float4 lg = *reinterpret_cast<const float4*>(&g_attn[(size_t)q * 128 + m * 16 + j * 4]);
    float mx = fmaxf(fmaxf(lg.x, lg.y), fmaxf(lg.z, lg.w));
    mx = fmaxf(mx, __shfl_xor_sync(0xffffffffu, mx, 1, 4));
    mx = fmaxf(mx, __shfl_xor_sync(0xffffffffu, mx, 2, 4));
    const float e0 = __expf(lg.x - mx), e1 = __expf(lg.y - mx);
    const float e2 = __expf(lg.z - mx), e3 = __expf(lg.w - mx);
    float sum = e0 + e1 + e2 + e3;
    sum += __shfl_xor_sync(0xffffffffu, sum, 1, 4);
    sum += __shfl_xor_sync(0xffffffffu, sum, 2, 4);
    const float inv = 1.f / sum;
    const float w0 = e0 * inv, w1 = e1 * inv, w2 = e2 * inv, w3 = e3 * inv;

    const float4 o0 = *reinterpret_cast<const float4*>(&g_off[(size_t)q * 256 + m * 32 + j * 8]);
    const float4 o1 = *reinterpret_cast<const float4*>(&g_off[(size_t)q * 256 + m * 32 + j * 8 + 4]);

    float acc[8];
    #pragma unroll
    for (int i = 0; i < 8; i++) acc[i] = 0.f;

    const __half* vbase = g_value + ((size_t)n * LEN_IN) * 256 + m * 32 + j * 8;

    #pragma unroll
    for (int l = 0; l < N_LEVELS; l++) {
        const int   Wi = c_W[l], Hi = c_H[l];
        const float Wf = (float)Wi, Hf = (float)Hi;
        const float2 r = *reinterpret_cast<const float2*>(&ref[((size_t)q * 4 + l) * 2]);
        const __half* vlev = vbase + (size_t)c_ST[l] * 256;

        #pragma unroll
        for (int p = 0; p < N_POINTS; p++) {
            const int pt = l * 4 + p;          // holder lane = pt>>2, slot = pt&3
            const int sl = pt & 3;
            const float wsel = (sl == 0) ? w0 : (sl == 1) ? w1 : (sl == 2) ? w2 : w3;
            const float oxsel = (sl == 0) ? o0.x : (sl == 1) ? o0.z : (sl == 2) ? o1.x : o1.z;
            const float oysel = (sl == 0) ? o0.y : (sl == 1) ? o0.w : (sl == 2) ? o1.y : o1.w;
            const float w_lp = __shfl_sync(0xffffffffu, wsel, pt >> 2, 4);
            const float ox   = __shfl_sync(0xffffffffu, oxsel, pt >> 2, 4);
            const float oy   = __shfl_sync(0xffffffffu, oysel, pt >> 2, 4);

            const float x = fmaf(r.x, Wf, ox) - 0.5f;
            const float y = fmaf(r.y, Hf, oy) - 0.5f;
            const float x0f = floorf(x);
            const float y0f = floorf(y);
            const float lx = x - x0f;
            const float ly = y - y0f;
            const int x0 = (int)x0f;
            const int y0 = (int)y0f;

            const float fx0 = ((unsigned)x0 < (unsigned)Wi) ? 1.f : 0.f;
            const float fx1 = ((unsigned)(x0 + 1) < (unsigned)Wi) ? 1.f : 0.f;
            const float fy0 = ((unsigned)y0 < (unsigned)Hi) ? 1.f : 0.f;
            const float fy1 = ((unsigned)(y0 + 1) < (unsigned)Hi) ? 1.f : 0.f;
            const int cx0 = min(max(x0, 0), Wi - 1);
            const int cx1 = min(max(x0 + 1, 0), Wi - 1);
            const int cy0 = min(max(y0, 0), Hi - 1);
            const int cy1 = min(max(y0 + 1, 0), Hi - 1);

            const float w00 = (1.f - lx) * (1.f - ly) * w_lp * (fx0 * fy0);
            const float w01 = lx * (1.f - ly) * w_lp * (fx1 * fy0);
            const float w10 = (1.f - lx) * ly * w_lp * (fx0 * fy1);
            const float w11 = lx * ly * w_lp * (fx1 * fy1);

            const __half* r0 = vlev + (size_t)(cy0 * Wi) * 256;
            const __half* r1 = vlev + (size_t)(cy1 * Wi) * 256;
            const uint4 v00 = *reinterpret_cast<const uint4*>(r0 + (size_t)cx0 * 256);
            const uint4 v01 = *reinterpret_cast<const uint4*>(r0 + (size_t)cx1 * 256);
            const uint4 v10 = *reinterpret_cast<const uint4*>(r1 + (size_t)cx0 * 256);
            const uint4 v11 = *reinterpret_cast<const uint4*>(r1 + (size_t)cx1 * 256);

            acc8(acc, v00, w00);
            acc8(acc, v01, w01);
            acc8(acc, v10, w10);
            acc8(acc, v11, w11);
        }
    }

    // write split bf16 (hi + lo) for the final GEMM's A operand
    uint32_t hp[4], lp[4];
    #pragma unroll
    for (int i = 0; i < 4; i++)
        split2(acc[2 * i], acc[2 * i + 1], hp[i], lp[i]);
    const size_t doff = (size_t)q * 256 + m * 32 + j * 8;
    *reinterpret_cast<uint4*>(&g_hhi[doff]) = make_uint4(hp[0], hp[1], hp[2], hp[3]);
    *reinterpret_cast<uint4*>(&g_hlo[doff]) = make_uint4(lp[0], lp[1], lp[2], lp[3]);
}

// ---------------- Launch --------------------------------------------------
extern "C" void kernel_launch(void* const* d_in, const int* in_sizes, int n_in,
                              void* d_out, int out_size)
{
    const float* query   = (const float*)d_in[0];
    const float* refpts  = (const float*)d_in[1];
    const float* inflat  = (const float*)d_in[2];
    const float* w_value = (const float*)d_in[5];
    const float* b_value = (const float*)d_in[6];
    const float* w_off   = (const float*)d_in[7];
    const float* b_off   = (const float*)d_in[8];
    const float* w_attn  = (const float*)d_in[9];
    const float* b_attn  = (const float*)d_in[10];
    const float* w_out   = (const float*)d_in[11];
    const float* b_out   = (const float*)d_in[12];
    float* out = (float*)d_out;

    const int SMEM = 2 * BUFB;   // 61440
    cudaFuncSetAttribute(front_gemm, cudaFuncAttributeMaxDynamicSharedMemorySize, SMEM);
    cudaFuncSetAttribute(final_gemm, cudaFuncAttributeMaxDynamicSharedMemorySize, SMEM);

    const int M = TOTQ;
    const int mblocks = (M + 127) / 128;   // 348

    prep_weights<<<896, 256>>>(w_value, w_off, w_attn, w_out);

    front_gemm<<<dim3(10, mblocks), 256, SMEM>>>(query, inflat, b_value, b_off, b_attn, M);

    const int nblocks = (TOTQ + 7) / 8;
    msda_sample<<<nblocks, 256>>>(refpts);

    final_gemm<<<dim3(4, mblocks), 256, SMEM>>>(b_out, out, M);
}

// round 11
// speedup vs baseline: 1.1106x; 1.1106x over previous
#include <cuda_runtime.h>
#include <cuda_bf16.h>
#include <cuda_fp16.h>
#include <cstdint>

// ---------------- Problem constants (fixed by the dataset) ----------------
#define D_MODEL   256
#define N_HEADS   8
#define HEAD_DIM  32
#define N_LEVELS  4
#define N_POINTS  4
#define LEN_IN    22223
#define NBATCH    2
#define TOTQ      (NBATCH * LEN_IN)   // 44446

__device__ __constant__ int   c_W[4] = {167, 84, 42, 21};
__device__ __constant__ int   c_H[4] = {100, 50, 25, 13};
__device__ __constant__ int   c_ST[4] = {0, 16700, 20900, 21950};

// ---------------- Scratch (device globals; no allocation allowed) ---------
__device__ __half g_value[(size_t)TOTQ * 256];   // fp16 value (written by GEMM)
__device__ float  g_off  [(size_t)TOTQ * 256];
__device__ float  g_attn [(size_t)TOTQ * 128];
__device__ __nv_bfloat16 g_hhi[(size_t)TOTQ * 256];  // sampled head out, split
__device__ __nv_bfloat16 g_hlo[(size_t)TOTQ * 256];
// split-bf16 weights, [n][k] row-major (k contiguous, 256 per row)
// [0,65536)=w_value  [65536,131072)=w_off  [131072,163840)=w_attn  [163840,229376)=w_out
__device__ __nv_bfloat16 g_bhi[229376];
__device__ __nv_bfloat16 g_blo[229376];

// ---------------- helpers ---------------------------------------------------
__device__ __forceinline__ uint32_t smem_u32(const void* p) {
    uint32_t a;
    asm("{ .reg .u64 t; cvta.to.shared.u64 t, %1; cvt.u32.u64 %0, t; }" : "=r"(a) : "l"(p));
    return a;
}
__device__ __forceinline__ void split2(float a, float b, uint32_t& hi, uint32_t& lo) {
    const __nv_bfloat16 ha = __float2bfloat16(a);
    const __nv_bfloat16 hb = __float2bfloat16(b);
    hi = ((uint32_t)__bfloat16_as_ushort(hb) << 16) | __bfloat16_as_ushort(ha);
    const __nv_bfloat16 la = __float2bfloat16(a - __bfloat162float(ha));
    const __nv_bfloat16 lb = __float2bfloat16(b - __bfloat162float(hb));
    lo = ((uint32_t)__bfloat16_as_ushort(lb) << 16) | __bfloat16_as_ushort(la);
}
__device__ __forceinline__ void ldm_x4(uint32_t* r, uint32_t addr) {
    asm volatile("ldmatrix.sync.aligned.m8n8.x4.shared.b16 {%0,%1,%2,%3}, [%4];"
                 : "=r"(r[0]), "=r"(r[1]), "=r"(r[2]), "=r"(r[3]) : "r"(addr));
}
__device__ __forceinline__ void mma_bf16(float* d, const uint32_t* a, uint32_t b0, uint32_t b1) {
    asm volatile(
        "mma.sync.aligned.m16n8k16.row.col.f32.bf16.bf16.f32 "
        "{%0,%1,%2,%3}, {%4,%5,%6,%7}, {%8,%9}, {%0,%1,%2,%3};"
        : "+f"(d[0]), "+f"(d[1]), "+f"(d[2]), "+f"(d[3])
        : "r"(a[0]), "r"(a[1]), "r"(a[2]), "r"(a[3]), "r"(b0), "r"(b1));
}
__device__ __forceinline__ void cp16(uint32_t dst, const void* src) {
    asm volatile("cp.async.cg.shared.global [%0], [%1], 16;" :: "r"(dst), "l"(src) : "memory");
}
#define CP_COMMIT() asm volatile("cp.async.commit_group;" ::: "memory")
#define CP_WAIT0()  asm volatile("cp.async.wait_group 0;" ::: "memory")

// ---------------- Weight prep: transpose + bf16 hi/lo split ----------------
__global__ void prep_weights(const float* __restrict__ wv, const float* __restrict__ wo,
                             const float* __restrict__ wa, const float* __restrict__ wu)
{
    const int idx = blockIdx.x * 256 + threadIdx.x;
    if (idx >= 229376) return;
    float a;
    if (idx < 65536)       { int l = idx;          int n = l >> 8, k = l & 255; a = wv[k * 256 + n]; }
    else if (idx < 131072) { int l = idx - 65536;  int n = l >> 8, k = l & 255; a = wo[k * 256 + n]; }
    else if (idx < 163840) { int l = idx - 131072; int n = l >> 8, k = l & 255; a = wa[k * 128 + n]; }
    else                   { int l = idx - 163840; int n = l >> 8, k = l & 255; a = wu[k * 256 + n]; }
    const __nv_bfloat16 h = __float2bfloat16(a);
    g_bhi[idx] = h;
    g_blo[idx] = __float2bfloat16(a - __bfloat162float(h));
}

// ---------------- HMMA GEMM: 128x128 CTA tile, BK=32 -----------------------
// 8 warps (4m x 2n), warp tile 32x64, m16n8k16. 3-pass split bf16.
#define SROW 80               // smem row stride (bytes): 32 bf16 + pad
#define REGN (128 * SROW)     // 10240 bytes per region
#define BUFB (4 * REGN)       // 40960 per buffer (Ah, Al, Bh, Bl)

struct GemmCtx {
    uint32_t sbase;
    int warp_m, warp_n, lane;
    uint32_t blane;
    float acc[2][8][4];
};

__device__ __forceinline__ void ctx_init(GemmCtx& g, const void* smem, int tid) {
    g.sbase = smem_u32(smem);
    const int wid = tid >> 5;
    g.lane = tid & 31;
    g.warp_m = wid & 3;
    g.warp_n = wid >> 2;
    g.blane = (uint32_t)(((g.lane & 7) + ((g.lane >> 4) << 3)) * SROW
                         + ((g.lane >> 3) & 1) * 16);
    #pragma unroll
    for (int i = 0; i < 2; i++)
        #pragma unroll
        for (int j = 0; j < 8; j++)
            #pragma unroll
            for (int k = 0; k < 4; k++) g.acc[i][j][k] = 0.f;
}

__device__ __forceinline__ void compute_chunk(GemmCtx& g, int b) {
    const uint32_t aAh = g.sbase + b * BUFB;
    const uint32_t aAl = aAh + REGN;
    const uint32_t aBh = aAh + 2 * REGN;
    const uint32_t aBl = aAh + 3 * REGN;
    #pragma unroll
    for (int ks = 0; ks < 2; ks++) {
        uint32_t ah[2][4], al[2][4];
        #pragma unroll
        for (int ma = 0; ma < 2; ma++) {
            const uint32_t ao = (uint32_t)((g.warp_m * 32 + ma * 16 + (g.lane & 15)) * SROW
                                           + ks * 32 + (g.lane >> 4) * 16);
            ldm_x4(ah[ma], aAh + ao);
            ldm_x4(al[ma], aAl + ao);
        }
        #pragma unroll
        for (int np = 0; np < 4; np++) {
            const uint32_t bo = g.blane + (uint32_t)((g.warp_n * 64 + np * 16) * SROW + ks * 32);
            uint32_t bh[4], bl[4];
            ldm_x4(bh, aBh + bo);
            ldm_x4(bl, aBl + bo);
            #pragma unroll
            for (int h = 0; h < 2; h++) {
                const int na = np * 2 + h;
                #pragma unroll
                for (int ma = 0; ma < 2; ma++) {
                    mma_bf16(g.acc[ma][na], ah[ma], bh[2 * h], bh[2 * h + 1]);
                    mma_bf16(g.acc[ma][na], al[ma], bh[2 * h], bh[2 * h + 1]);
                    mma_bf16(g.acc[ma][na], ah[ma], bl[2 * h], bl[2 * h + 1]);
                }
            }
        }
    }
}

template<typename OutT>
__device__ __forceinline__ void epilogue(GemmCtx& g, const float* bias, OutT* C,
                                         int M, int N, int bm, int bn) {
    #pragma unroll
    for (int ma = 0; ma < 2; ma++) {
        const int row0 = bm + g.warp_m * 32 + ma * 16 + (g.lane >> 2);
        const int row1 = row0 + 8;
        #pragma unroll
        for (int na = 0; na < 8; na++) {
            const int col = bn + g.warp_n * 64 + na * 8 + 2 * (g.lane & 3);
            const float2 bv = *reinterpret_cast<const float2*>(bias + col);
            if constexpr (sizeof(OutT) == 2) {
                if (row0 < M) {
                    __half2 o = __floats2half2_rn(g.acc[ma][na][0] + bv.x, g.acc[ma][na][1] + bv.y);
                    *reinterpret_cast<__half2*>(&C[(size_t)row0 * N + col]) = o;
                }
                if (row1 < M) {
                    __half2 o = __floats2half2_rn(g.acc[ma][na][2] + bv.x, g.acc[ma][na][3] + bv.y);
                    *reinterpret_cast<__half2*>(&C[(size_t)row1 * N + col]) = o;
                }
            } else {
                if (row0 < M) {
                    float2 o = make_float2(g.acc[ma][na][0] + bv.x, g.acc[ma][na][1] + bv.y);
                    *reinterpret_cast<float2*>(&C[(size_t)row0 * N + col]) = o;
                }
                if (row1 < M) {
                    float2 o = make_float2(g.acc[ma][na][2] + bv.x, g.acc[ma][na][3] + bv.y);
                    *reinterpret_cast<float2*>(&C[(size_t)row1 * N + col]) = o;
                }
            }
        }
    }
}

// ---- front GEMM: A fp32 (split in-kernel), B pre-split (round-9 body) -----
template<typename OutT>
__device__ __forceinline__ void gemm_f32A(
    const float* __restrict__ A,
    const __nv_bfloat16* __restrict__ Bhi,
    const __nv_bfloat16* __restrict__ Blo,
    const float* __restrict__ bias,
    OutT* __restrict__ C,
    int M, int N, int bm, int bn)
{
    extern __shared__ uint8_t dyns[];
    const int tid = threadIdx.x;
    GemmCtx g;
    ctx_init(g, dyns, tid);

    const int arow  = tid >> 1;
    const int akseg = (tid & 1) * 16;
    const int gr    = bm + arow;
    const int bn0   = tid >> 2;
    const int bs0   = tid & 3;
    const int bn1   = (256 + tid) >> 2;
    const int bs1   = (256 + tid) & 3;

    float4 f[4];

    auto issue_B = [&](int c, int b) {
        const int k0 = c * 32;
        const uint32_t dBh = g.sbase + b * BUFB + 2 * REGN;
        const uint32_t dBl = dBh + REGN;
        const size_t g0 = (size_t)(bn + bn0) * 256 + k0 + bs0 * 8;
        const size_t g1 = (size_t)(bn + bn1) * 256 + k0 + bs1 * 8;
        const uint32_t o0 = bn0 * SROW + bs0 * 16;
        const uint32_t o1 = bn1 * SROW + bs1 * 16;
        cp16(dBh + o0, Bhi + g0);
        cp16(dBl + o0, Blo + g0);
        cp16(dBh + o1, Bhi + g1);
        cp16(dBl + o1, Blo + g1);
        CP_COMMIT();
    };
    auto load_A = [&](int c) {
        const int k0 = c * 32;
        if (gr < M) {
            const float4* s = reinterpret_cast<const float4*>(A + (size_t)gr * 256 + k0 + akseg);
            f[0] = s[0]; f[1] = s[1]; f[2] = s[2]; f[3] = s[3];
        } else {
            f[0] = f[1] = f[2] = f[3] = make_float4(0.f, 0.f, 0.f, 0.f);
        }
    };
    auto store_A = [&](int b) {
        uint8_t* sAh = dyns + b * BUFB;
        uint8_t* sAl = sAh + REGN;
        uint32_t hp[8], lp[8];
        split2(f[0].x, f[0].y, hp[0], lp[0]);
        split2(f[0].z, f[0].w, hp[1], lp[1]);
        split2(f[1].x, f[1].y, hp[2], lp[2]);
        split2(f[1].z, f[1].w, hp[3], lp[3]);
        split2(f[2].x, f[2].y, hp[4], lp[4]);
        split2(f[2].z, f[2].w, hp[5], lp[5]);
        split2(f[3].x, f[3].y, hp[6], lp[6]);
        split2(f[3].z, f[3].w, hp[7], lp[7]);
        const int aoff = arow * SROW + akseg * 2;
        *reinterpret_cast<uint4*>(sAh + aoff)      = make_uint4(hp[0], hp[1], hp[2], hp[3]);
        *reinterpret_cast<uint4*>(sAh + aoff + 16) = make_uint4(hp[4], hp[5], hp[6], hp[7]);
        *reinterpret_cast<uint4*>(sAl + aoff)      = make_uint4(lp[0], lp[1], lp[2], lp[3]);
        *reinterpret_cast<uint4*>(sAl + aoff + 16) = make_uint4(lp[4], lp[5], lp[6], lp[7]);
    };

    issue_B(0, 0);
    load_A(0);
    store_A(0);
    CP_WAIT0();
    __syncthreads();

    #pragma unroll 1
    for (int c = 0; c < 8; c++) {
        const int b = c & 1;
        if (c < 7) {
            issue_B(c + 1, b ^ 1);
            load_A(c + 1);
        }
        compute_chunk(g, b);
        if (c < 7) {
            store_A(b ^ 1);
            CP_WAIT0();
            __syncthreads();
        }
    }
    epilogue(g, bias, C, M, N, bm, bn);
}

// ---- final GEMM: A pre-split bf16 (cp.async), B pre-split ------------------
__device__ __forceinline__ void gemm_splitA(
    const __nv_bfloat16* __restrict__ Ahi,
    const __nv_bfloat16* __restrict__ Alo,
    const __nv_bfloat16* __restrict__ Bhi,
    const __nv_bfloat16* __restrict__ Blo,
    const float* __restrict__ bias,
    float* __restrict__ C,
    int M, int N, int bm, int bn)
{
    extern __shared__ uint8_t dyns[];
    const int tid = threadIdx.x;
    GemmCtx g;
    ctx_init(g, dyns, tid);

    const int r0 = tid >> 2;            // 0..63
    const int s0 = tid & 3;
    const int r1 = (256 + tid) >> 2;    // 64..127
    const int s1 = (256 + tid) & 3;

    auto issue_chunk = [&](int c, int b) {
        const int k0 = c * 32;
        const uint32_t dAh = g.sbase + b * BUFB;
        const uint32_t dAl = dAh + REGN;
        const uint32_t dBh = dAh + 2 * REGN;
        const uint32_t dBl = dAh + 3 * REGN;
        // A: 512 x 16B per region -> 2 per thread per region
        {
            const uint32_t so0 = r0 * SROW + s0 * 16;
            const uint32_t so1 = r1 * SROW + s1 * 16;
            const size_t ga0 = (size_t)(bm + r0) * 256 + k0 + s0 * 8;
            const size_t ga1 = (size_t)(bm + r1) * 256 + k0 + s1 * 8;
            if (bm + r0 < M) { cp16(dAh + so0, Ahi + ga0); cp16(dAl + so0, Alo + ga0); }
            if (bm + r1 < M) { cp16(dAh + so1, Ahi + ga1); cp16(dAl + so1, Alo + ga1); }
        }
        // B: 512 x 16B per region -> 2 per thread per region
        {
            const uint32_t so0 = r0 * SROW + s0 * 16;
            const uint32_t so1 = r1 * SROW + s1 * 16;
            const size_t gb0 = (size_t)(bn + r0) * 256 + k0 + s0 * 8;
            const size_t gb1 = (size_t)(bn + r1) * 256 + k0 + s1 * 8;
            cp16(dBh + so0, Bhi + gb0);
            cp16(dBl + so0, Blo + gb0);
            cp16(dBh + so1, Bhi + gb1);
            cp16(dBl + so1, Blo + gb1);
        }
        CP_COMMIT();
    };

    issue_chunk(0, 0);
    CP_WAIT0();
    __syncthreads();

    #pragma unroll 1
    for (int c = 0; c < 8; c++) {
        const int b = c & 1;
        if (c < 7) issue_chunk(c + 1, b ^ 1);
        compute_chunk(g, b);
        if (c < 7) {
            CP_WAIT0();
            __syncthreads();
        }
    }
    epilogue(g, bias, C, M, N, bm, bn);
}

// Fused front GEMMs: grid.x = 5  (0,1: value->fp16 | 2,3: offsets | 4: attn)
__global__ __launch_bounds__(256, 2)
void front_gemm(const float* __restrict__ query,
                const float* __restrict__ inflat,
                const float* __restrict__ b_value,
                const float* __restrict__ b_off,
                const float* __restrict__ b_attn,
                int M)
{
    const int bx = blockIdx.x;
    const int bm = blockIdx.y * 128;
    if (bx < 2) {
        gemm_f32A<__half>(inflat, g_bhi, g_blo, b_value, g_value, M, 256, bm, bx * 128);
    } else if (bx < 4) {
        gemm_f32A<float>(query, g_bhi + 65536, g_blo + 65536, b_off, g_off, M, 256, bm, (bx - 2) * 128);
    } else {
        gemm_f32A<float>(query, g_bhi + 131072, g_blo + 131072, b_attn, g_attn, M, 128, bm, 0);
    }
}

// Final GEMM: out = head @ w_out + b_out   (A pre-split by sampling kernel)
__global__ __launch_bounds__(256, 2)
void final_gemm(const float* __restrict__ b_out, float* __restrict__ out, int M)
{
    gemm_splitA(g_hhi, g_hlo, g_bhi + 163840, g_blo + 163840, b_out, out,
                M, 256, blockIdx.y * 128, blockIdx.x * 128);
}

// ---------------- Sampling kernel -----------------------------------------
// One warp per query. lane = head*4 + quad; each lane handles 8 fp16 channels.
// Writes g_hhi/g_hlo (bf16 split) for the final GEMM.
__device__ __forceinline__ void acc8(float* a, const uint4& v, float w) {
    const __half2* h = reinterpret_cast<const __half2*>(&v);
    #pragma unroll
    for (int i = 0; i < 4; i++) {
        const float2 f = __half22float2(h[i]);
        a[2 * i]     = fmaf(f.x, w, a[2 * i]);
        a[2 * i + 1] = fmaf(f.y, w, a[2 * i + 1]);
    }
}

__global__ __launch_bounds__(256)
void msda_sample(const float* __restrict__ ref)
{
    const int q = blockIdx.x * 8 + (threadIdx.x >> 5);
    if (q >= TOTQ) return;
    const int lane = threadIdx.x & 31;
    const int m = lane >> 2;        // head 0..7
    const int j = lane & 3;         // quad 0..3 (8 channels)
    const int n = (q >= LEN_IN) ? 1 : 0;

    const float4 lg = *reinterpret_cast<const float4*>(&g_attn[(size_t)q * 128 + m * 16 + j * 4]);
    float mx = fmaxf(fmaxf(lg.x, lg.y), fmaxf(lg.z, lg.w));
    mx = fmaxf(mx, __shfl_xor_sync(0xffffffffu, mx, 1, 4));
    mx = fmaxf(mx, __shfl_xor_sync(0xffffffffu, mx, 2, 4));
    const float e0 = __expf(lg.x - mx), e1 = __expf(lg.y - mx);
    const float e2 = __expf(lg.z - mx), e3 = __expf(lg.w - mx);
    float sum = e0 + e1 + e2 + e3;
    sum += __shfl_xor_sync(0xffffffffu, sum, 1, 4);
    sum += __shfl_xor_sync(0xffffffffu, sum, 2, 4);
    const float inv = 1.f / sum;
    const float w0 = e0 * inv, w1 = e1 * inv, w2 = e2 * inv, w3 = e3 * inv;

    const float4 o0 = *reinterpret_cast<const float4*>(&g_off[(size_t)q * 256 + m * 32 + j * 8]);
    const float4 o1 = *reinterpret_cast<const float4*>(&g_off[(size_t)q * 256 + m * 32 + j * 8 + 4]);

    float acc[8];
    #pragma unroll
    for (int i = 0; i < 8; i++) acc[i] = 0.f;

    const __half* vbase = g_value + ((size_t)n * LEN_IN) * 256 + m * 32 + j * 8;

    #pragma unroll
    for (int l = 0; l < N_LEVELS; l++) {
        const int   Wi = c_W[l], Hi = c_H[l];
        const float Wf = (float)Wi, Hf = (float)Hi;
        const float2 r = *reinterpret_cast<const float2*>(&ref[((size_t)q * 4 + l) * 2]);
        const __half* vlev = vbase + (size_t)c_ST[l] * 256;

        #pragma unroll
        for (int p = 0; p < N_POINTS; p++) {
            const int pt = l * 4 + p;          // holder lane = pt>>2, slot = pt&3
            const int sl = pt & 3;
            const float wsel = (sl == 0) ? w0 : (sl == 1) ? w1 : (sl == 2) ? w2 : w3;
            const float oxsel = (sl == 0) ? o0.x : (sl == 1) ? o0.z : (sl == 2) ? o1.x : o1.z;
            const float oysel = (sl == 0) ? o0.y : (sl == 1) ? o0.w : (sl == 2) ? o1.y : o1.w;
            const float w_lp = __shfl_sync(0xffffffffu, wsel, pt >> 2, 4);
            const float ox   = __shfl_sync(0xffffffffu, oxsel, pt >> 2, 4);
            const float oy   = __shfl_sync(0xffffffffu, oysel, pt >> 2, 4);

            const float x = fmaf(r.x, Wf, ox) - 0.5f;
            const float y = fmaf(r.y, Hf, oy) - 0.5f;
            const float x0f = floorf(x);
            const float y0f = floorf(y);
            const float lx = x - x0f;
            const float ly = y - y0f;
            const int x0 = (int)x0f;
            const int y0 = (int)y0f;

            const float fx0 = ((unsigned)x0 < (unsigned)Wi) ? 1.f : 0.f;
            const float fx1 = ((unsigned)(x0 + 1) < (unsigned)Wi) ? 1.f : 0.f;
            const float fy0 = ((unsigned)y0 < (unsigned)Hi) ? 1.f : 0.f;
            const float fy1 = ((unsigned)(y0 + 1) < (unsigned)Hi) ? 1.f : 0.f;
            const int cx0 = min(max(x0, 0), Wi - 1);
            const int cx1 = min(max(x0 + 1, 0), Wi - 1);
            const int cy0 = min(max(y0, 0), Hi - 1);
            const int cy1 = min(max(y0 + 1, 0), Hi - 1);

            const float w00 = (1.f - lx) * (1.f - ly) * w_lp * (fx0 * fy0);
            const float w01 = lx * (1.f - ly) * w_lp * (fx1 * fy0);
            const float w10 = (1.f - lx) * ly * w_lp * (fx0 * fy1);
            const float w11 = lx * ly * w_lp * (fx1 * fy1);

            const __half* r0 = vlev + (size_t)(cy0 * Wi) * 256;
            const __half* r1 = vlev + (size_t)(cy1 * Wi) * 256;
            const uint4 v00 = *reinterpret_cast<const uint4*>(r0 + (size_t)cx0 * 256);
            const uint4 v01 = *reinterpret_cast<const uint4*>(r0 + (size_t)cx1 * 256);
            const uint4 v10 = *reinterpret_cast<const uint4*>(r1 + (size_t)cx0 * 256);
            const uint4 v11 = *reinterpret_cast<const uint4*>(r1 + (size_t)cx1 * 256);

            acc8(acc, v00, w00);
            acc8(acc, v01, w01);
            acc8(acc, v10, w10);
            acc8(acc, v11, w11);
        }
    }

    // write split bf16 (hi + lo) for the final GEMM's A operand
    uint32_t hp[4], lp[4];
    #pragma unroll
    for (int i = 0; i < 4; i++)
        split2(acc[2 * i], acc[2 * i + 1], hp[i], lp[i]);
    const size_t doff = (size_t)q * 256 + m * 32 + j * 8;
    *reinterpret_cast<uint4*>(&g_hhi[doff]) = make_uint4(hp[0], hp[1], hp[2], hp[3]);
    *reinterpret_cast<uint4*>(&g_hlo[doff]) = make_uint4(lp[0], lp[1], lp[2], lp[3]);
}

// ---------------- Launch --------------------------------------------------
extern "C" void kernel_launch(void* const* d_in, const int* in_sizes, int n_in,
                              void* d_out, int out_size)
{
    const float* query   = (const float*)d_in[0];
    const float* refpts  = (const float*)d_in[1];
    const float* inflat  = (const float*)d_in[2];
    const float* w_value = (const float*)d_in[5];
    const float* b_value = (const float*)d_in[6];
    const float* w_off   = (const float*)d_in[7];
    const float* b_off   = (const float*)d_in[8];
    const float* w_attn  = (const float*)d_in[9];
    const float* b_attn  = (const float*)d_in[10];
    const float* w_out   = (const float*)d_in[11];
    const float* b_out   = (const float*)d_in[12];
    float* out = (float*)d_out;

    const int SMEM = 2 * BUFB;   // 81920
    cudaFuncSetAttribute(front_gemm, cudaFuncAttributeMaxDynamicSharedMemorySize, SMEM);
    cudaFuncSetAttribute(final_gemm, cudaFuncAttributeMaxDynamicSharedMemorySize, SMEM);

    const int M = TOTQ;
    const int mblocks = (M + 127) / 128;   // 348

    prep_weights<<<896, 256>>>(w_value, w_off, w_attn, w_out);

    front_gemm<<<dim3(5, mblocks), 256, SMEM>>>(query, inflat, b_value, b_off, b_attn, M);

    const int nblocks = (TOTQ + 7) / 8;
    msda_sample<<<nblocks, 256>>>(refpts);

    final_gemm<<<dim3(2, mblocks), 256, SMEM>>>(b_out, out, M);
}

// round 12
// speedup vs baseline: 1.3079x; 1.1776x over previous
#include <cuda_runtime.h>
#include <cuda_bf16.h>
#include <cuda_fp16.h>
#include <cstdint>

// ---------------- Problem constants (fixed by the dataset) ----------------
#define D_MODEL   256
#define N_HEADS   8
#define HEAD_DIM  32
#define N_LEVELS  4
#define N_POINTS  4
#define LEN_IN    22223
#define NBATCH    2
#define TOTQ      (NBATCH * LEN_IN)   // 44446

__device__ __constant__ int   c_W[4] = {167, 84, 42, 21};
__device__ __constant__ int   c_H[4] = {100, 50, 25, 13};
__device__ __constant__ int   c_ST[4] = {0, 16700, 20900, 21950};

// ---------------- Scratch (device globals; no allocation allowed) ---------
__device__ __half g_value[(size_t)TOTQ * 256];   // fp16 value (written by GEMM)
__device__ float  g_off  [(size_t)TOTQ * 256];
__device__ float  g_attn [(size_t)TOTQ * 128];
__device__ __half g_hhi[(size_t)TOTQ * 256];     // sampled head out, fp16 split
__device__ __half g_hlo[(size_t)TOTQ * 256];
// fp16 weights, [n][k] row-major (k contiguous, 256 per row)
// [0,65536)=w_value  [65536,131072)=w_off  [131072,163840)=w_attn  [163840,229376)=w_out
__device__ __half g_bh[229376];

// ---------------- helpers ---------------------------------------------------
__device__ __forceinline__ uint32_t smem_u32(const void* p) {
    uint32_t a;
    asm("{ .reg .u64 t; cvta.to.shared.u64 t, %1; cvt.u32.u64 %0, t; }" : "=r"(a) : "l"(p));
    return a;
}
// fp16 hi/lo split of two floats, packed
__device__ __forceinline__ void splitH(float a, float b, uint32_t& hi, uint32_t& lo) {
    const __half ha = __float2half_rn(a);
    const __half hb = __float2half_rn(b);
    hi = ((uint32_t)__half_as_ushort(hb) << 16) | __half_as_ushort(ha);
    const __half la = __float2half_rn(a - __half2float(ha));
    const __half lb = __float2half_rn(b - __half2float(hb));
    lo = ((uint32_t)__half_as_ushort(lb) << 16) | __half_as_ushort(la);
}
__device__ __forceinline__ void ldm_x4(uint32_t* r, uint32_t addr) {
    asm volatile("ldmatrix.sync.aligned.m8n8.x4.shared.b16 {%0,%1,%2,%3}, [%4];"
                 : "=r"(r[0]), "=r"(r[1]), "=r"(r[2]), "=r"(r[3]) : "r"(addr));
}
__device__ __forceinline__ void mma_fp16(float* d, const uint32_t* a, uint32_t b0, uint32_t b1) {
    asm volatile(
        "mma.sync.aligned.m16n8k16.row.col.f32.f16.f16.f32 "
        "{%0,%1,%2,%3}, {%4,%5,%6,%7}, {%8,%9}, {%0,%1,%2,%3};"
        : "+f"(d[0]), "+f"(d[1]), "+f"(d[2]), "+f"(d[3])
        : "r"(a[0]), "r"(a[1]), "r"(a[2]), "r"(a[3]), "r"(b0), "r"(b1));
}
__device__ __forceinline__ void cp16(uint32_t dst, const void* src) {
    asm volatile("cp.async.cg.shared.global [%0], [%1], 16;" :: "r"(dst), "l"(src) : "memory");
}
#define CP_COMMIT() asm volatile("cp.async.commit_group;" ::: "memory")
#define CP_WAIT0()  asm volatile("cp.async.wait_group 0;" ::: "memory")

// ---------------- Weight prep: transpose + fp16 round ----------------------
__global__ void prep_weights(const float* __restrict__ wv, const float* __restrict__ wo,
                             const float* __restrict__ wa, const float* __restrict__ wu)
{
    const int idx = blockIdx.x * 256 + threadIdx.x;
    if (idx >= 229376) return;
    float a;
    if (idx < 65536)       { int l = idx;          int n = l >> 8, k = l & 255; a = wv[k * 256 + n]; }
    else if (idx < 131072) { int l = idx - 65536;  int n = l >> 8, k = l & 255; a = wo[k * 256 + n]; }
    else if (idx < 163840) { int l = idx - 131072; int n = l >> 8, k = l & 255; a = wa[k * 128 + n]; }
    else                   { int l = idx - 163840; int n = l >> 8, k = l & 255; a = wu[k * 256 + n]; }
    g_bh[idx] = __float2half_rn(a);
}

// ---------------- HMMA GEMM: 128x128 CTA tile, BK=32 -----------------------
// 8 warps (4m x 2n), warp tile 32x64, m16n8k16. 2-pass fp16 split:
// D = ah*bh + al*bh  =  a * fp16(b)   (A split exact; only B rounding remains)
#define SROW 80               // smem row stride (bytes): 32 halves + pad
#define REGN (128 * SROW)     // 10240 bytes per region
#define BUFB (3 * REGN)       // 30720 per buffer (Ah, Al, Bh)

struct GemmCtx {
    uint32_t sbase;
    int warp_m, warp_n, lane;
    uint32_t blane;
    float acc[2][8][4];
};

__device__ __forceinline__ void ctx_init(GemmCtx& g, const void* smem, int tid) {
    g.sbase = smem_u32(smem);
    const int wid = tid >> 5;
    g.lane = tid & 31;
    g.warp_m = wid & 3;
    g.warp_n = wid >> 2;
    g.blane = (uint32_t)(((g.lane & 7) + ((g.lane >> 4) << 3)) * SROW
                         + ((g.lane >> 3) & 1) * 16);
    #pragma unroll
    for (int i = 0; i < 2; i++)
        #pragma unroll
        for (int j = 0; j < 8; j++)
            #pragma unroll
            for (int k = 0; k < 4; k++) g.acc[i][j][k] = 0.f;
}

__device__ __forceinline__ void compute_chunk(GemmCtx& g, int b) {
    const uint32_t aAh = g.sbase + b * BUFB;
    const uint32_t aAl = aAh + REGN;
    const uint32_t aBh = aAh + 2 * REGN;
    #pragma unroll
    for (int ks = 0; ks < 2; ks++) {
        uint32_t ah[2][4], al[2][4];
        #pragma unroll
        for (int ma = 0; ma < 2; ma++) {
            const uint32_t ao = (uint32_t)((g.warp_m * 32 + ma * 16 + (g.lane & 15)) * SROW
                                           + ks * 32 + (g.lane >> 4) * 16);
            ldm_x4(ah[ma], aAh + ao);
            ldm_x4(al[ma], aAl + ao);
        }
        #pragma unroll
        for (int np = 0; np < 4; np++) {
            const uint32_t bo = g.blane + (uint32_t)((g.warp_n * 64 + np * 16) * SROW + ks * 32);
            uint32_t bh[4];
            ldm_x4(bh, aBh + bo);
            #pragma unroll
            for (int h = 0; h < 2; h++) {
                const int na = np * 2 + h;
                #pragma unroll
                for (int ma = 0; ma < 2; ma++) {
                    mma_fp16(g.acc[ma][na], ah[ma], bh[2 * h], bh[2 * h + 1]);
                    mma_fp16(g.acc[ma][na], al[ma], bh[2 * h], bh[2 * h + 1]);
                }
            }
        }
    }
}

template<typename OutT>
__device__ __forceinline__ void epilogue(GemmCtx& g, const float* bias, OutT* C,
                                         int M, int N, int bm, int bn) {
    #pragma unroll
    for (int ma = 0; ma < 2; ma++) {
        const int row0 = bm + g.warp_m * 32 + ma * 16 + (g.lane >> 2);
        const int row1 = row0 + 8;
        #pragma unroll
        for (int na = 0; na < 8; na++) {
            const int col = bn + g.warp_n * 64 + na * 8 + 2 * (g.lane & 3);
            const float2 bv = *reinterpret_cast<const float2*>(bias + col);
            if constexpr (sizeof(OutT) == 2) {
                if (row0 < M) {
                    __half2 o = __floats2half2_rn(g.acc[ma][na][0] + bv.x, g.acc[ma][na][1] + bv.y);
                    *reinterpret_cast<__half2*>(&C[(size_t)row0 * N + col]) = o;
                }
                if (row1 < M) {
                    __half2 o = __floats2half2_rn(g.acc[ma][na][2] + bv.x, g.acc[ma][na][3] + bv.y);
                    *reinterpret_cast<__half2*>(&C[(size_t)row1 * N + col]) = o;
                }
            } else {
                if (row0 < M) {
                    float2 o = make_float2(g.acc[ma][na][0] + bv.x, g.acc[ma][na][1] + bv.y);
                    *reinterpret_cast<float2*>(&C[(size_t)row0 * N + col]) = o;
                }
                if (row1 < M) {
                    float2 o = make_float2(g.acc[ma][na][2] + bv.x, g.acc[ma][na][3] + bv.y);
                    *reinterpret_cast<float2*>(&C[(size_t)row1 * N + col]) = o;
                }
            }
        }
    }
}

// ---- front GEMM: A fp32 (fp16-split in-kernel), B fp16 ---------------------
template<typename OutT>
__device__ __forceinline__ void gemm_f32A(
    const float* __restrict__ A,
    const __half* __restrict__ Bh,
    const float* __restrict__ bias,
    OutT* __restrict__ C,
    int M, int N, int bm, int bn)
{
    extern __shared__ uint8_t dyns[];
    const int tid = threadIdx.x;
    GemmCtx g;
    ctx_init(g, dyns, tid);

    const int arow  = tid >> 1;
    const int akseg = (tid & 1) * 16;
    const int gr    = bm + arow;
    const int bn0   = tid >> 2;
    const int bs0   = tid & 3;
    const int bn1   = (256 + tid) >> 2;
    const int bs1   = (256 + tid) & 3;

    float4 f[4];

    auto issue_B = [&](int c, int b) {
        const int k0 = c * 32;
        const uint32_t dBh = g.sbase + b * BUFB + 2 * REGN;
        const size_t g0 = (size_t)(bn + bn0) * 256 + k0 + bs0 * 8;
        const size_t g1 = (size_t)(bn + bn1) * 256 + k0 + bs1 * 8;
        cp16(dBh + bn0 * SROW + bs0 * 16, Bh + g0);
        cp16(dBh + bn1 * SROW + bs1 * 16, Bh + g1);
        CP_COMMIT();
    };
    auto load_A = [&](int c) {
        const int k0 = c * 32;
        if (gr < M) {
            const float4* s = reinterpret_cast<const float4*>(A + (size_t)gr * 256 + k0 + akseg);
            f[0] = s[0]; f[1] = s[1]; f[2] = s[2]; f[3] = s[3];
        } else {
            f[0] = f[1] = f[2] = f[3] = make_float4(0.f, 0.f, 0.f, 0.f);
        }
    };
    auto store_A = [&](int b) {
        uint8_t* sAh = dyns + b * BUFB;
        uint8_t* sAl = sAh + REGN;
        uint32_t hp[8], lp[8];
        splitH(f[0].x, f[0].y, hp[0], lp[0]);
        splitH(f[0].z, f[0].w, hp[1], lp[1]);
        splitH(f[1].x, f[1].y, hp[2], lp[2]);
        splitH(f[1].z, f[1].w, hp[3], lp[3]);
        splitH(f[2].x, f[2].y, hp[4], lp[4]);
        splitH(f[2].z, f[2].w, hp[5], lp[5]);
        splitH(f[3].x, f[3].y, hp[6], lp[6]);
        splitH(f[3].z, f[3].w, hp[7], lp[7]);
        const int aoff = arow * SROW + akseg * 2;
        *reinterpret_cast<uint4*>(sAh + aoff)      = make_uint4(hp[0], hp[1], hp[2], hp[3]);
        *reinterpret_cast<uint4*>(sAh + aoff + 16) = make_uint4(hp[4], hp[5], hp[6], hp[7]);
        *reinterpret_cast<uint4*>(sAl + aoff)      = make_uint4(lp[0], lp[1], lp[2], lp[3]);
        *reinterpret_cast<uint4*>(sAl + aoff + 16) = make_uint4(lp[4], lp[5], lp[6], lp[7]);
    };

    issue_B(0, 0);
    load_A(0);
    store_A(0);
    CP_WAIT0();
    __syncthreads();

    #pragma unroll 1
    for (int c = 0; c < 8; c++) {
        const int b = c & 1;
        if (c < 7) {
            issue_B(c + 1, b ^ 1);
            load_A(c + 1);
        }
        compute_chunk(g, b);
        if (c < 7) {
            store_A(b ^ 1);
            CP_WAIT0();
            __syncthreads();
        }
    }
    epilogue(g, bias, C, M, N, bm, bn);
}

// ---- final GEMM: A pre-split fp16 (cp.async), B fp16 -----------------------
__device__ __forceinline__ void gemm_splitA(
    const __half* __restrict__ Ahi,
    const __half* __restrict__ Alo,
    const __half* __restrict__ Bh,
    const float* __restrict__ bias,
    float* __restrict__ C,
    int M, int N, int bm, int bn)
{
    extern __shared__ uint8_t dyns[];
    const int tid = threadIdx.x;
    GemmCtx g;
    ctx_init(g, dyns, tid);

    const int r0 = tid >> 2;            // 0..63
    const int s0 = tid & 3;
    const int r1 = (256 + tid) >> 2;    // 64..127
    const int s1 = (256 + tid) & 3;

    auto issue_chunk = [&](int c, int b) {
        const int k0 = c * 32;
        const uint32_t dAh = g.sbase + b * BUFB;
        const uint32_t dAl = dAh + REGN;
        const uint32_t dBh = dAh + 2 * REGN;
        const uint32_t so0 = r0 * SROW + s0 * 16;
        const uint32_t so1 = r1 * SROW + s1 * 16;
        // A hi/lo
        const size_t ga0 = (size_t)(bm + r0) * 256 + k0 + s0 * 8;
        const size_t ga1 = (size_t)(bm + r1) * 256 + k0 + s1 * 8;
        if (bm + r0 < M) { cp16(dAh + so0, Ahi + ga0); cp16(dAl + so0, Alo + ga0); }
        if (bm + r1 < M) { cp16(dAh + so1, Ahi + ga1); cp16(dAl + so1, Alo + ga1); }
        // B
        const size_t gb0 = (size_t)(bn + r0) * 256 + k0 + s0 * 8;
        const size_t gb1 = (size_t)(bn + r1) * 256 + k0 + s1 * 8;
        cp16(dBh + so0, Bh + gb0);
        cp16(dBh + so1, Bh + gb1);
        CP_COMMIT();
    };

    issue_chunk(0, 0);
    CP_WAIT0();
    __syncthreads();

    #pragma unroll 1
    for (int c = 0; c < 8; c++) {
        const int b = c & 1;
        if (c < 7) issue_chunk(c + 1, b ^ 1);
        compute_chunk(g, b);
        if (c < 7) {
            CP_WAIT0();
            __syncthreads();
        }
    }
    epilogue(g, bias, C, M, N, bm, bn);
}

// Fused front GEMMs: grid.x = 5  (0,1: value->fp16 | 2,3: offsets | 4: attn)
__global__ __launch_bounds__(256, 2)
void front_gemm(const float* __restrict__ query,
                const float* __restrict__ inflat,
                const float* __restrict__ b_value,
                const float* __restrict__ b_off,
                const float* __restrict__ b_attn,
                int M)
{
    const int bx = blockIdx.x;
    const int bm = blockIdx.y * 128;
    if (bx < 2) {
        gemm_f32A<__half>(inflat, g_bh, b_value, g_value, M, 256, bm, bx * 128);
    } else if (bx < 4) {
        gemm_f32A<float>(query, g_bh + 65536, b_off, g_off, M, 256, bm, (bx - 2) * 128);
    } else {
        gemm_f32A<float>(query, g_bh + 131072, b_attn, g_attn, M, 128, bm, 0);
    }
}

// Final GEMM: out = head @ w_out + b_out   (A pre-split by sampling kernel)
__global__ __launch_bounds__(256, 2)
void final_gemm(const float* __restrict__ b_out, float* __restrict__ out, int M)
{
    gemm_splitA(g_hhi, g_hlo, g_bh + 163840, b_out, out,
                M, 256, blockIdx.y * 128, blockIdx.x * 128);
}

// ---------------- Sampling kernel -----------------------------------------
// One warp per query. lane = head*4 + quad; each lane handles 8 fp16 channels.
// Writes g_hhi/g_hlo (fp16 split) for the final GEMM.
__device__ __forceinline__ void acc8(float* a, const uint4& v, float w) {
    const __half2* h = reinterpret_cast<const __half2*>(&v);
    #pragma unroll
    for (int i = 0; i < 4; i++) {
        const float2 f = __half22float2(h[i]);
        a[2 * i]     = fmaf(f.x, w, a[2 * i]);
        a[2 * i + 1] = fmaf(f.y, w, a[2 * i + 1]);
    }
}

__global__ __launch_bounds__(256)
void msda_sample(const float* __restrict__ ref)
{
    const int q = blockIdx.x * 8 + (threadIdx.x >> 5);
    if (q >= TOTQ) return;
    const int lane = threadIdx.x & 31;
    const int m = lane >> 2;        // head 0..7
    const int j = lane & 3;         // quad 0..3 (8 channels)
    const int n = (q >= LEN_IN) ? 1 : 0;

    const float4 lg = *reinterpret_cast<const float4*>(&g_attn[(size_t)q * 128 + m * 16 + j * 4]);
    float mx = fmaxf(fmaxf(lg.x, lg.y), fmaxf(lg.z, lg.w));
    mx = fmaxf(mx, __shfl_xor_sync(0xffffffffu, mx, 1, 4));
    mx = fmaxf(mx, __shfl_xor_sync(0xffffffffu, mx, 2, 4));
    const float e0 = __expf(lg.x - mx), e1 = __expf(lg.y - mx);
    const float e2 = __expf(lg.z - mx), e3 = __expf(lg.w - mx);
    float sum = e0 + e1 + e2 + e3;
    sum += __shfl_xor_sync(0xffffffffu, sum, 1, 4);
    sum += __shfl_xor_sync(0xffffffffu, sum, 2, 4);
    const float inv = 1.f / sum;
    const float w0 = e0 * inv, w1 = e1 * inv, w2 = e2 * inv, w3 = e3 * inv;

    const float4 o0 = *reinterpret_cast<const float4*>(&g_off[(size_t)q * 256 + m * 32 + j * 8]);
    const float4 o1 = *reinterpret_cast<const float4*>(&g_off[(size_t)q * 256 + m * 32 + j * 8 + 4]);

    float acc[8];
    #pragma unroll
    for (int i = 0; i < 8; i++) acc[i] = 0.f;

    const __half* vbase = g_value + ((size_t)n * LEN_IN) * 256 + m * 32 + j * 8;

    #pragma unroll
    for (int l = 0; l < N_LEVELS; l++) {
        const int   Wi = c_W[l], Hi = c_H[l];
        const float Wf = (float)Wi, Hf = (float)Hi;
        const float2 r = *reinterpret_cast<const float2*>(&ref[((size_t)q * 4 + l) * 2]);
        const __half* vlev = vbase + (size_t)c_ST[l] * 256;

        #pragma unroll
        for (int p = 0; p < N_POINTS; p++) {
            const int pt = l * 4 + p;          // holder lane = pt>>2, slot = pt&3
            const int sl = pt & 3;
            const float wsel = (sl == 0) ? w0 : (sl == 1) ? w1 : (sl == 2) ? w2 : w3;
            const float oxsel = (sl == 0) ? o0.x : (sl == 1) ? o0.z : (sl == 2) ? o1.x : o1.z;
            const float oysel = (sl == 0) ? o0.y : (sl == 1) ? o0.w : (sl == 2) ? o1.y : o1.w;
            const float w_lp = __shfl_sync(0xffffffffu, wsel, pt >> 2, 4);
            const float ox   = __shfl_sync(0xffffffffu, oxsel, pt >> 2, 4);
            const float oy   = __shfl_sync(0xffffffffu, oysel, pt >> 2, 4);

            const float x = fmaf(r.x, Wf, ox) - 0.5f;
            const float y = fmaf(r.y, Hf, oy) - 0.5f;
            const float x0f = floorf(x);
            const float y0f = floorf(y);
            const float lx = x - x0f;
            const float ly = y - y0f;
            const int x0 = (int)x0f;
            const int y0 = (int)y0f;

            const float fx0 = ((unsigned)x0 < (unsigned)Wi) ? 1.f : 0.f;
            const float fx1 = ((unsigned)(x0 + 1) < (unsigned)Wi) ? 1.f : 0.f;
            const float fy0 = ((unsigned)y0 < (unsigned)Hi) ? 1.f : 0.f;
            const float fy1 = ((unsigned)(y0 + 1) < (unsigned)Hi) ? 1.f : 0.f;
            const int cx0 = min(max(x0, 0), Wi - 1);
            const int cx1 = min(max(x0 + 1, 0), Wi - 1);
            const int cy0 = min(max(y0, 0), Hi - 1);
            const int cy1 = min(max(y0 + 1, 0), Hi - 1);

            const float w00 = (1.f - lx) * (1.f - ly) * w_lp * (fx0 * fy0);
            const float w01 = lx * (1.f - ly) * w_lp * (fx1 * fy0);
            const float w10 = (1.f - lx) * ly * w_lp * (fx0 * fy1);
            const float w11 = lx * ly * w_lp * (fx1 * fy1);

            const __half* r0 = vlev + (size_t)(cy0 * Wi) * 256;
            const __half* r1 = vlev + (size_t)(cy1 * Wi) * 256;
            const uint4 v00 = *reinterpret_cast<const uint4*>(r0 + (size_t)cx0 * 256);
            const uint4 v01 = *reinterpret_cast<const uint4*>(r0 + (size_t)cx1 * 256);
            const uint4 v10 = *reinterpret_cast<const uint4*>(r1 + (size_t)cx0 * 256);
            const uint4 v11 = *reinterpret_cast<const uint4*>(r1 + (size_t)cx1 * 256);

            acc8(acc, v00, w00);
            acc8(acc, v01, w01);
            acc8(acc, v10, w10);
            acc8(acc, v11, w11);
        }
    }

    // write fp16 split (hi + lo) for the final GEMM's A operand
    uint32_t hp[4], lp[4];
    #pragma unroll
    for (int i = 0; i < 4; i++)
        splitH(acc[2 * i], acc[2 * i + 1], hp[i], lp[i]);
    const size_t doff = (size_t)q * 256 + m * 32 + j * 8;
    *reinterpret_cast<uint4*>(&g_hhi[doff]) = make_uint4(hp[0], hp[1], hp[2], hp[3]);
    *reinterpret_cast<uint4*>(&g_hlo[doff]) = make_uint4(lp[0], lp[1], lp[2], lp[3]);
}

// ---------------- Launch --------------------------------------------------
extern "C" void kernel_launch(void* const* d_in, const int* in_sizes, int n_in,
                              void* d_out, int out_size)
{
    const float* query   = (const float*)d_in[0];
    const float* refpts  = (const float*)d_in[1];
    const float* inflat  = (const float*)d_in[2];
    const float* w_value = (const float*)d_in[5];
    const float* b_value = (const float*)d_in[6];
    const float* w_off   = (const float*)d_in[7];
    const float* b_off   = (const float*)d_in[8];
    const float* w_attn  = (const float*)d_in[9];
    const float* b_attn  = (const float*)d_in[10];
    const float* w_out   = (const float*)d_in[11];
    const float* b_out   = (const float*)d_in[12];
    float* out = (float*)d_out;

    const int SMEM = 2 * BUFB;   // 61440
    cudaFuncSetAttribute(front_gemm, cudaFuncAttributeMaxDynamicSharedMemorySize, SMEM);
    cudaFuncSetAttribute(final_gemm, cudaFuncAttributeMaxDynamicSharedMemorySize, SMEM);

    const int M = TOTQ;
    const int mblocks = (M + 127) / 128;   // 348

    prep_weights<<<896, 256>>>(w_value, w_off, w_attn, w_out);

    front_gemm<<<dim3(5, mblocks), 256, SMEM>>>(query, inflat, b_value, b_off, b_attn, M);

    const int nblocks = (TOTQ + 7) / 8;
    msda_sample<<<nblocks, 256>>>(refpts);

    final_gemm<<<dim3(2, mblocks), 256, SMEM>>>(b_out, out, M);
}

// round 15
// speedup vs baseline: 1.4265x; 1.0907x over previous
#include <cuda_runtime.h>
#include <cuda_bf16.h>
#include <cuda_fp16.h>
#include <cstdint>

// ---------------- Problem constants (fixed by the dataset) ----------------
#define D_MODEL   256
#define N_HEADS   8
#define HEAD_DIM  32
#define N_LEVELS  4
#define N_POINTS  4
#define LEN_IN    22223
#define NBATCH    2
#define TOTQ      (NBATCH * LEN_IN)   // 44446

__device__ __constant__ int   c_W[4] = {167, 84, 42, 21};
__device__ __constant__ int   c_H[4] = {100, 50, 25, 13};
__device__ __constant__ int   c_ST[4] = {0, 16700, 20900, 21950};

// ---------------- Scratch (device globals; no allocation allowed) ---------
__device__ __half g_value[(size_t)TOTQ * 256];   // fp16 value (written by GEMM)
__device__ float  g_off  [(size_t)TOTQ * 256];
__device__ float  g_attn [(size_t)TOTQ * 128];
__device__ __half g_hhi[(size_t)TOTQ * 256];     // sampled head out, fp16 split
__device__ __half g_hlo[(size_t)TOTQ * 256];
// fp16 weights, [n][k] row-major (k contiguous, 256 per row)
// [0,65536)=w_value  [65536,131072)=w_off  [131072,163840)=w_attn  [163840,229376)=w_out
__device__ __half g_bh[229376];

// ---------------- helpers ---------------------------------------------------
__device__ __forceinline__ uint32_t smem_u32(const void* p) {
    uint32_t a;
    asm("{ .reg .u64 t; cvta.to.shared.u64 t, %1; cvt.u32.u64 %0, t; }" : "=r"(a) : "l"(p));
    return a;
}
// fp16 hi/lo split of two floats, packed
__device__ __forceinline__ void splitH(float a, float b, uint32_t& hi, uint32_t& lo) {
    const __half ha = __float2half_rn(a);
    const __half hb = __float2half_rn(b);
    hi = ((uint32_t)__half_as_ushort(hb) << 16) | __half_as_ushort(ha);
    const __half la = __float2half_rn(a - __half2float(ha));
    const __half lb = __float2half_rn(b - __half2float(hb));
    lo = ((uint32_t)__half_as_ushort(lb) << 16) | __half_as_ushort(la);
}
__device__ __forceinline__ uint32_t packH(float a, float b) {
    const __half2 h = __floats2half2_rn(a, b);
    return *reinterpret_cast<const uint32_t*>(&h);
}
__device__ __forceinline__ void ldm_x4(uint32_t* r, uint32_t addr) {
    asm volatile("ldmatrix.sync.aligned.m8n8.x4.shared.b16 {%0,%1,%2,%3}, [%4];"
                 : "=r"(r[0]), "=r"(r[1]), "=r"(r[2]), "=r"(r[3]) : "r"(addr));
}
__device__ __forceinline__ void mma_fp16(float* d, const uint32_t* a, uint32_t b0, uint32_t b1) {
    asm volatile(
        "mma.sync.aligned.m16n8k16.row.col.f32.f16.f16.f32 "
        "{%0,%1,%2,%3}, {%4,%5,%6,%7}, {%8,%9}, {%0,%1,%2,%3};"
        : "+f"(d[0]), "+f"(d[1]), "+f"(d[2]), "+f"(d[3])
        : "r"(a[0]), "r"(a[1]), "r"(a[2]), "r"(a[3]), "r"(b0), "r"(b1));
}
__device__ __forceinline__ void cp16(uint32_t dst, const void* src) {
    asm volatile("cp.async.cg.shared.global [%0], [%1], 16;" :: "r"(dst), "l"(src) : "memory");
}
#define CP_COMMIT() asm volatile("cp.async.commit_group;" ::: "memory")
#define CP_WAIT0()  asm volatile("cp.async.wait_group 0;" ::: "memory")

// ---------------- Weight prep: transpose + fp16 round ----------------------
__global__ void prep_weights(const float* __restrict__ wv, const float* __restrict__ wo,
                             const float* __restrict__ wa, const float* __restrict__ wu)
{
    const int idx = blockIdx.x * 256 + threadIdx.x;
    if (idx >= 229376) return;
    float a;
    if (idx < 65536)       { int l = idx;          int n = l >> 8, k = l & 255; a = wv[k * 256 + n]; }
    else if (idx < 131072) { int l = idx - 65536;  int n = l >> 8, k = l & 255; a = wo[k * 256 + n]; }
    else if (idx < 163840) { int l = idx - 131072; int n = l >> 8, k = l & 255; a = wa[k * 128 + n]; }
    else                   { int l = idx - 163840; int n = l >> 8, k = l & 255; a = wu[k * 256 + n]; }
    g_bh[idx] = __float2half_rn(a);
}

// ---------------- GEMM common ----------------------------------------------
// 128x128 CTA tile, BK=32, 8 warps (4m x 2n), warp tile 32x64, m16n8k16.
#define SROW 80               // smem row stride (bytes): 32 halves + pad
#define REGN (128 * SROW)     // 10240 bytes per region
#define BUF1 (2 * REGN)       // front buffer: A, B
#define BUF2 (3 * REGN)       // final buffer: Ah, Al, B

struct GemmCtx {
    uint32_t sbase;
    int warp_m, warp_n, lane;
    uint32_t blane;
    float acc[2][8][4];
};

__device__ __forceinline__ void ctx_init(GemmCtx& g, const void* smem, int tid) {
    g.sbase = smem_u32(smem);
    const int wid = tid >> 5;
    g.lane = tid & 31;
    g.warp_m = wid & 3;
    g.warp_n = wid >> 2;
    g.blane = (uint32_t)(((g.lane & 7) + ((g.lane >> 4) << 3)) * SROW
                         + ((g.lane >> 3) & 1) * 16);
    #pragma unroll
    for (int i = 0; i < 2; i++)
        #pragma unroll
        for (int j = 0; j < 8; j++)
            #pragma unroll
            for (int k = 0; k < 4; k++) g.acc[i][j][k] = 0.f;
}

// single-pass chunk: A at base, B at base+REGN
__device__ __forceinline__ void compute_chunk1(GemmCtx& g, int b) {
    const uint32_t aA = g.sbase + b * BUF1;
    const uint32_t aB = aA + REGN;
    #pragma unroll
    for (int ks = 0; ks < 2; ks++) {
        uint32_t ah[2][4];
        #pragma unroll
        for (int ma = 0; ma < 2; ma++) {
            const uint32_t ao = (uint32_t)((g.warp_m * 32 + ma * 16 + (g.lane & 15)) * SROW
                                           + ks * 32 + (g.lane >> 4) * 16);
            ldm_x4(ah[ma], aA + ao);
        }
        #pragma unroll
        for (int np = 0; np < 4; np++) {
            const uint32_t bo = g.blane + (uint32_t)((g.warp_n * 64 + np * 16) * SROW + ks * 32);
            uint32_t bh[4];
            ldm_x4(bh, aB + bo);
            #pragma unroll
            for (int h = 0; h < 2; h++) {
                const int na = np * 2 + h;
                #pragma unroll
                for (int ma = 0; ma < 2; ma++)
                    mma_fp16(g.acc[ma][na], ah[ma], bh[2 * h], bh[2 * h + 1]);
            }
        }
    }
}

// 2-pass chunk: Ah, Al, B
__device__ __forceinline__ void compute_chunk2(GemmCtx& g, int b) {
    const uint32_t aAh = g.sbase + b * BUF2;
    const uint32_t aAl = aAh + REGN;
    const uint32_t aBh = aAh + 2 * REGN;
    #pragma unroll
    for (int ks = 0; ks < 2; ks++) {
        uint32_t ah[2][4], al[2][4];
        #pragma unroll
        for (int ma = 0; ma < 2; ma++) {
            const uint32_t ao = (uint32_t)((g.warp_m * 32 + ma * 16 + (g.lane & 15)) * SROW
                                           + ks * 32 + (g.lane >> 4) * 16);
            ldm_x4(ah[ma], aAh + ao);
            ldm_x4(al[ma], aAl + ao);
        }
        #pragma unroll
        for (int np = 0; np < 4; np++) {
            const uint32_t bo = g.blane + (uint32_t)((g.warp_n * 64 + np * 16) * SROW + ks * 32);
            uint32_t bh[4];
            ldm_x4(bh, aBh + bo);
            #pragma unroll
            for (int h = 0; h < 2; h++) {
                const int na = np * 2 + h;
                #pragma unroll
                for (int ma = 0; ma < 2; ma++) {
                    mma_fp16(g.acc[ma][na], ah[ma], bh[2 * h], bh[2 * h + 1]);
                    mma_fp16(g.acc[ma][na], al[ma], bh[2 * h], bh[2 * h + 1]);
                }
            }
        }
    }
}

template<typename OutT>
__device__ __forceinline__ void epilogue(GemmCtx& g, const float* bias, OutT* C,
                                         int M, int N, int bm, int bn) {
    #pragma unroll
    for (int ma = 0; ma < 2; ma++) {
        const int row0 = bm + g.warp_m * 32 + ma * 16 + (g.lane >> 2);
        const int row1 = row0 + 8;
        #pragma unroll
        for (int na = 0; na < 8; na++) {
            const int col = bn + g.warp_n * 64 + na * 8 + 2 * (g.lane & 3);
            const float2 bv = *reinterpret_cast<const float2*>(bias + col);
            if constexpr (sizeof(OutT) == 2) {
                if (row0 < M) {
                    __half2 o = __floats2half2_rn(g.acc[ma][na][0] + bv.x, g.acc[ma][na][1] + bv.y);
                    *reinterpret_cast<__half2*>(&C[(size_t)row0 * N + col]) = o;
                }
                if (row1 < M) {
                    __half2 o = __floats2half2_rn(g.acc[ma][na][2] + bv.x, g.acc[ma][na][3] + bv.y);
                    *reinterpret_cast<__half2*>(&C[(size_t)row1 * N + col]) = o;
                }
            } else {
                if (row0 < M) {
                    float2 o = make_float2(g.acc[ma][na][0] + bv.x, g.acc[ma][na][1] + bv.y);
                    *reinterpret_cast<float2*>(&C[(size_t)row0 * N + col]) = o;
                }
                if (row1 < M) {
                    float2 o = make_float2(g.acc[ma][na][2] + bv.x, g.acc[ma][na][3] + bv.y);
                    *reinterpret_cast<float2*>(&C[(size_t)row1 * N + col]) = o;
                }
            }
        }
    }
}

// ---- front GEMM: A fp32 -> fp16 (single pass), B fp16 ----------------------
template<typename OutT>
__device__ __forceinline__ void gemm_f32A(
    const float* __restrict__ A,
    const __half* __restrict__ Bh,
    const float* __restrict__ bias,
    OutT* __restrict__ C,
    int M, int N, int bm, int bn)
{
    extern __shared__ uint8_t dyns[];
    const int tid = threadIdx.x;
    GemmCtx g;
    ctx_init(g, dyns, tid);

    const int arow  = tid >> 1;
    const int akseg = (tid & 1) * 16;
    const int gr    = bm + arow;
    const int bn0   = tid >> 2;
    const int bs0   = tid & 3;
    const int bn1   = (256 + tid) >> 2;
    const int bs1   = (256 + tid) & 3;

    float4 f[4];

    auto issue_B = [&](int c, int b) {
        const int k0 = c * 32;
        const uint32_t dB = g.sbase + b * BUF1 + REGN;
        const size_t g0 = (size_t)(bn + bn0) * 256 + k0 + bs0 * 8;
        const size_t g1 = (size_t)(bn + bn1) * 256 + k0 + bs1 * 8;
        cp16(dB + bn0 * SROW + bs0 * 16, Bh + g0);
        cp16(dB + bn1 * SROW + bs1 * 16, Bh + g1);
        CP_COMMIT();
    };
    auto load_A = [&](int c) {
        const int k0 = c * 32;
        if (gr < M) {
            const float4* s = reinterpret_cast<const float4*>(A + (size_t)gr * 256 + k0 + akseg);
            f[0] = s[0]; f[1] = s[1]; f[2] = s[2]; f[3] = s[3];
        } else {
            f[0] = f[1] = f[2] = f[3] = make_float4(0.f, 0.f, 0.f, 0.f);
        }
    };
    auto store_A = [&](int b) {
        uint8_t* sA = dyns + b * BUF1;
        const int aoff = arow * SROW + akseg * 2;
        *reinterpret_cast<uint4*>(sA + aoff) = make_uint4(
            packH(f[0].x, f[0].y), packH(f[0].z, f[0].w),
            packH(f[1].x, f[1].y), packH(f[1].z, f[1].w));
        *reinterpret_cast<uint4*>(sA + aoff + 16) = make_uint4(
            packH(f[2].x, f[2].y), packH(f[2].z, f[2].w),
            packH(f[3].x, f[3].y), packH(f[3].z, f[3].w));
    };

    issue_B(0, 0);
    load_A(0);
    store_A(0);
    CP_WAIT0();
    __syncthreads();

    #pragma unroll 1
    for (int c = 0; c < 8; c++) {
        const int b = c & 1;
        if (c < 7) {
            issue_B(c + 1, b ^ 1);
            load_A(c + 1);
        }
        compute_chunk1(g, b);
        if (c < 7) {
            store_A(b ^ 1);
            CP_WAIT0();
            __syncthreads();
        }
    }
    epilogue(g, bias, C, M, N, bm, bn);
}

// ---- final GEMM: A pre-split fp16 (cp.async), B fp16, 2-pass ---------------
__device__ __forceinline__ void gemm_splitA(
    const __half* __restrict__ Ahi,
    const __half* __restrict__ Alo,
    const __half* __restrict__ Bh,
    const float* __restrict__ bias,
    float* __restrict__ C,
    int M, int N, int bm, int bn)
{
    extern __shared__ uint8_t dyns[];
    const int tid = threadIdx.x;
    GemmCtx g;
    ctx_init(g, dyns, tid);

    const int r0 = tid >> 2;            // 0..63
    const int s0 = tid & 3;
    const int r1 = (256 + tid) >> 2;    // 64..127
    const int s1 = (256 + tid) & 3;

    auto issue_chunk = [&](int c, int b) {
        const int k0 = c * 32;
        const uint32_t dAh = g.sbase + b * BUF2;
        const uint32_t dAl = dAh + REGN;
        const uint32_t dB  = dAh + 2 * REGN;
        const uint32_t so0 = r0 * SROW + s0 * 16;
        const uint32_t so1 = r1 * SROW + s1 * 16;
        const size_t ga0 = (size_t)(bm + r0) * 256 + k0 + s0 * 8;
        const size_t ga1 = (size_t)(bm + r1) * 256 + k0 + s1 * 8;
        if (bm + r0 < M) { cp16(dAh + so0, Ahi + ga0); cp16(dAl + so0, Alo + ga0); }
        if (bm + r1 < M) { cp16(dAh + so1, Ahi + ga1); cp16(dAl + so1, Alo + ga1); }
        const size_t gb0 = (size_t)(bn + r0) * 256 + k0 + s0 * 8;
        const size_t gb1 = (size_t)(bn + r1) * 256 + k0 + s1 * 8;
        cp16(dB + so0, Bh + gb0);
        cp16(dB + so1, Bh + gb1);
        CP_COMMIT();
    };

    issue_chunk(0, 0);
    CP_WAIT0();
    __syncthreads();

    #pragma unroll 1
    for (int c = 0; c < 8; c++) {
        const int b = c & 1;
        if (c < 7) issue_chunk(c + 1, b ^ 1);
        compute_chunk2(g, b);
        if (c < 7) {
            CP_WAIT0();
            __syncthreads();
        }
    }
    epilogue(g, bias, C, M, N, bm, bn);
}

// Fused front GEMMs: grid.x = 5  (0,1: value->fp16 | 2,3: offsets | 4: attn)
__global__ __launch_bounds__(256, 2)
void front_gemm(const float* __restrict__ query,
                const float* __restrict__ inflat,
                const float* __restrict__ b_value,
                const float* __restrict__ b_off,
                const float* __restrict__ b_attn,
                int M)
{
    const int bx = blockIdx.x;
    const int bm = blockIdx.y * 128;
    if (bx < 2) {
        gemm_f32A<__half>(inflat, g_bh, b_value, g_value, M, 256, bm, bx * 128);
    } else if (bx < 4) {
        gemm_f32A<float>(query, g_bh + 65536, b_off, g_off, M, 256, bm, (bx - 2) * 128);
    } else {
        gemm_f32A<float>(query, g_bh + 131072, b_attn, g_attn, M, 128, bm, 0);
    }
}

// Final GEMM: out = head @ w_out + b_out   (A pre-split by sampling kernel)
__global__ __launch_bounds__(256, 2)
void final_gemm(const float* __restrict__ b_out, float* __restrict__ out, int M)
{
    gemm_splitA(g_hhi, g_hlo, g_bh + 163840, b_out, out,
                M, 256, blockIdx.y * 128, blockIdx.x * 128);
}

// ---------------- Sampling kernel -----------------------------------------
// One warp per query. lane = head*4 + quad; each lane handles 8 fp16 channels.
// Writes g_hhi/g_hlo (fp16 split) for the final GEMM.
__device__ __forceinline__ void acc8(float* a, const uint4& v, float w) {
    const __half2* h = reinterpret_cast<const __half2*>(&v);
    #pragma unroll
    for (int i = 0; i < 4; i++) {
        const float2 f = __half22float2(h[i]);
        a[2 * i]     = fmaf(f.x, w, a[2 * i]);
        a[2 * i + 1] = fmaf(f.y, w, a[2 * i + 1]);
    }
}

__global__ __launch_bounds__(256)
void msda_sample(const float* __restrict__ ref)
{
    const int q = blockIdx.x * 8 + (threadIdx.x >> 5);
    if (q >= TOTQ) return;
    const int lane = threadIdx.x & 31;
    const int m = lane >> 2;        // head 0..7
    const int j = lane & 3;         // quad 0..3 (8 channels)
    const int n = (q >= LEN_IN) ? 1 : 0;

    const float4 lg = *reinterpret_cast<const float4*>(&g_attn[(size_t)q * 128 + m * 16 + j * 4]);
    float mx = fmaxf(fmaxf(lg.x, lg.y), fmaxf(lg.z, lg.w));
    mx = fmaxf(mx, __shfl_xor_sync(0xffffffffu, mx, 1, 4));
    mx = fmaxf(mx, __shfl_xor_sync(0xffffffffu, mx, 2, 4));
    const float e0 = __expf(lg.x - mx), e1 = __expf(lg.y - mx);
    const float e2 = __expf(lg.z - mx), e3 = __expf(lg.w - mx);
    float sum = e0 + e1 + e2 + e3;
    sum += __shfl_xor_sync(0xffffffffu, sum, 1, 4);
    sum += __shfl_xor_sync(0xffffffffu, sum, 2, 4);
    const float inv = 1.f / sum;
    const float w0 = e0 * inv, w1 = e1 * inv, w2 = e2 * inv, w3 = e3 * inv;

    const float4 o0 = *reinterpret_cast<const float4*>(&g_off[(size_t)q * 256 + m * 32 + j * 8]);
    const float4 o1 = *reinterpret_cast<const float4*>(&g_off[(size_t)q * 256 + m * 32 + j * 8 + 4]);

    float acc[8];
    #pragma unroll
    for (int i = 0; i < 8; i++) acc[i] = 0.f;

    const __half* vbase = g_value + ((size_t)n * LEN_IN) * 256 + m * 32 + j * 8;

    #pragma unroll
    for (int l = 0; l < N_LEVELS; l++) {
        const int   Wi = c_W[l], Hi = c_H[l];
        const float Wf = (float)Wi, Hf = (float)Hi;
        const float2 r = *reinterpret_cast<const float2*>(&ref[((size_t)q * 4 + l) * 2]);
        const __half* vlev = vbase + (size_t)c_ST[l] * 256;

        #pragma unroll
        for (int p = 0; p < N_POINTS; p++) {
            const int pt = l * 4 + p;          // holder lane = pt>>2, slot = pt&3
            const int sl = pt & 3;
            const float wsel = (sl == 0) ? w0 : (sl == 1) ? w1 : (sl == 2) ? w2 : w3;
            const float oxsel = (sl == 0) ? o0.x : (sl == 1) ? o0.z : (sl == 2) ? o1.x : o1.z;
            const float oysel = (sl == 0) ? o0.y : (sl == 1) ? o0.w : (sl == 2) ? o1.y : o1.w;
            const float w_lp = __shfl_sync(0xffffffffu, wsel, pt >> 2, 4);
            const float ox   = __shfl_sync(0xffffffffu, oxsel, pt >> 2, 4);
            const float oy   = __shfl_sync(0xffffffffu, oysel, pt >> 2, 4);

            const float x = fmaf(r.x, Wf, ox) - 0.5f;
            const float y = fmaf(r.y, Hf, oy) - 0.5f;
            const float x0f = floorf(x);
            const float y0f = floorf(y);
            const float lx = x - x0f;
            const float ly = y - y0f;
            const int x0 = (int)x0f;
            const int y0 = (int)y0f;

            const float fx0 = ((unsigned)x0 < (unsigned)Wi) ? 1.f : 0.f;
            const float fx1 = ((unsigned)(x0 + 1) < (unsigned)Wi) ? 1.f : 0.f;
            const float fy0 = ((unsigned)y0 < (unsigned)Hi) ? 1.f : 0.f;
            const float fy1 = ((unsigned)(y0 + 1) < (unsigned)Hi) ? 1.f : 0.f;
            const int cx0 = min(max(x0, 0), Wi - 1);
            const int cx1 = min(max(x0 + 1, 0), Wi - 1);
            const int cy0 = min(max(y0, 0), Hi - 1);
            const int cy1 = min(max(y0 + 1, 0), Hi - 1);

            const float w00 = (1.f - lx) * (1.f - ly) * w_lp * (fx0 * fy0);
            const float w01 = lx * (1.f - ly) * w_lp * (fx1 * fy0);
            const float w10 = (1.f - lx) * ly * w_lp * (fx0 * fy1);
            const float w11 = lx * ly * w_lp * (fx1 * fy1);

            const __half* r0 = vlev + (size_t)(cy0 * Wi) * 256;
            const __half* r1 = vlev + (size_t)(cy1 * Wi) * 256;
            const uint4 v00 = *reinterpret_cast<const uint4*>(r0 + (size_t)cx0 * 256);
            const uint4 v01 = *reinterpret_cast<const uint4*>(r0 + (size_t)cx1 * 256);
            const uint4 v10 = *reinterpret_cast<const uint4*>(r1 + (size_t)cx0 * 256);
            const uint4 v11 = *reinterpret_cast<const uint4*>(r1 + (size_t)cx1 * 256);

            acc8(acc, v00, w00);
            acc8(acc, v01, w01);
            acc8(acc, v10, w10);
            acc8(acc, v11, w11);
        }
    }

    // write fp16 split (hi + lo) for the final GEMM's A operand
    uint32_t hp[4], lp[4];
    #pragma unroll
    for (int i = 0; i < 4; i++)
        splitH(acc[2 * i], acc[2 * i + 1], hp[i], lp[i]);
    const size_t doff = (size_t)q * 256 + m * 32 + j * 8;
    *reinterpret_cast<uint4*>(&g_hhi[doff]) = make_uint4(hp[0], hp[1], hp[2], hp[3]);
    *reinterpret_cast<uint4*>(&g_hlo[doff]) = make_uint4(lp[0], lp[1], lp[2], lp[3]);
}

// ---------------- Launch --------------------------------------------------
extern "C" void kernel_launch(void* const* d_in, const int* in_sizes, int n_in,
                              void* d_out, int out_size)
{
    const float* query   = (const float*)d_in[0];
    const float* refpts  = (const float*)d_in[1];
    const float* inflat  = (const float*)d_in[2];
    const float* w_value = (const float*)d_in[5];
    const float* b_value = (const float*)d_in[6];
    const float* w_off   = (const float*)d_in[7];
    const float* b_off   = (const float*)d_in[8];
    const float* w_attn  = (const float*)d_in[9];
    const float* b_attn  = (const float*)d_in[10];
    const float* w_out   = (const float*)d_in[11];
    const float* b_out   = (const float*)d_in[12];
    float* out = (float*)d_out;

    const int SMEM1 = 2 * BUF1;   // 40960 (front)
    const int SMEM2 = 2 * BUF2;   // 61440 (final)
    cudaFuncSetAttribute(front_gemm, cudaFuncAttributeMaxDynamicSharedMemorySize, SMEM1);
    cudaFuncSetAttribute(final_gemm, cudaFuncAttributeMaxDynamicSharedMemorySize, SMEM2);

    const int M = TOTQ;
    const int mblocks = (M + 127) / 128;   // 348

    prep_weights<<<896, 256>>>(w_value, w_off, w_attn, w_out);

    front_gemm<<<dim3(5, mblocks), 256, SMEM1>>>(query, inflat, b_value, b_off, b_attn, M);

    const int nblocks = (TOTQ + 7) / 8;
    msda_sample<<<nblocks, 256>>>(refpts);

    final_gemm<<<dim3(2, mblocks), 256, SMEM2>>>(b_out, out, M);
}

// round 16
// speedup vs baseline: 1.5147x; 1.0619x over previous
#include <cuda_runtime.h>
#include <cuda_bf16.h>
#include <cuda_fp16.h>
#include <cstdint>

// ---------------- Problem constants (fixed by the dataset) ----------------
#define D_MODEL   256
#define N_HEADS   8
#define HEAD_DIM  32
#define N_LEVELS  4
#define N_POINTS  4
#define LEN_IN    22223
#define NBATCH    2
#define TOTQ      (NBATCH * LEN_IN)   // 44446

__device__ __constant__ int   c_W[4] = {167, 84, 42, 21};
__device__ __constant__ int   c_H[4] = {100, 50, 25, 13};
__device__ __constant__ int   c_ST[4] = {0, 16700, 20900, 21950};

// ---------------- Scratch (device globals; no allocation allowed) ---------
__device__ __half g_value[(size_t)TOTQ * 256];   // fp16 value (written by GEMM)
__device__ float  g_off  [(size_t)TOTQ * 256];
__device__ float  g_attn [(size_t)TOTQ * 128];
__device__ __half g_head_h[(size_t)TOTQ * 256];  // sampled head out, fp16
// fp16 weights, [n][k] row-major (k contiguous, 256 per row)
// [0,65536)=w_value  [65536,131072)=w_off  [131072,163840)=w_attn  [163840,229376)=w_out
__device__ __half g_bh[229376];

// ---------------- helpers ---------------------------------------------------
__device__ __forceinline__ uint32_t smem_u32(const void* p) {
    uint32_t a;
    asm("{ .reg .u64 t; cvta.to.shared.u64 t, %1; cvt.u32.u64 %0, t; }" : "=r"(a) : "l"(p));
    return a;
}
__device__ __forceinline__ uint32_t packH(float a, float b) {
    const __half2 h = __floats2half2_rn(a, b);
    return *reinterpret_cast<const uint32_t*>(&h);
}
__device__ __forceinline__ void ldm_x4(uint32_t* r, uint32_t addr) {
    asm volatile("ldmatrix.sync.aligned.m8n8.x4.shared.b16 {%0,%1,%2,%3}, [%4];"
                 : "=r"(r[0]), "=r"(r[1]), "=r"(r[2]), "=r"(r[3]) : "r"(addr));
}
__device__ __forceinline__ void mma_fp16(float* d, const uint32_t* a, uint32_t b0, uint32_t b1) {
    asm volatile(
        "mma.sync.aligned.m16n8k16.row.col.f32.f16.f16.f32 "
        "{%0,%1,%2,%3}, {%4,%5,%6,%7}, {%8,%9}, {%0,%1,%2,%3};"
        : "+f"(d[0]), "+f"(d[1]), "+f"(d[2]), "+f"(d[3])
        : "r"(a[0]), "r"(a[1]), "r"(a[2]), "r"(a[3]), "r"(b0), "r"(b1));
}
__device__ __forceinline__ void cp16(uint32_t dst, const void* src) {
    asm volatile("cp.async.cg.shared.global [%0], [%1], 16;" :: "r"(dst), "l"(src) : "memory");
}
#define CP_COMMIT() asm volatile("cp.async.commit_group;" ::: "memory")
#define CP_WAIT0()  asm volatile("cp.async.wait_group 0;" ::: "memory")

// ---------------- Weight prep: transpose + fp16 round ----------------------
__global__ void prep_weights(const float* __restrict__ wv, const float* __restrict__ wo,
                             const float* __restrict__ wa, const float* __restrict__ wu)
{
    const int idx = blockIdx.x * 256 + threadIdx.x;
    if (idx >= 229376) return;
    float a;
    if (idx < 65536)       { int l = idx;          int n = l >> 8, k = l & 255; a = wv[k * 256 + n]; }
    else if (idx < 131072) { int l = idx - 65536;  int n = l >> 8, k = l & 255; a = wo[k * 256 + n]; }
    else if (idx < 163840) { int l = idx - 131072; int n = l >> 8, k = l & 255; a = wa[k * 128 + n]; }
    else                   { int l = idx - 163840; int n = l >> 8, k = l & 255; a = wu[k * 256 + n]; }
    g_bh[idx] = __float2half_rn(a);
}

// ---------------- GEMM common ----------------------------------------------
// 128x128 CTA tile, BK=32, 8 warps (4m x 2n), warp tile 32x64, m16n8k16.
// Single-pass fp16 (A and B rounded to fp16, fp32 accumulate).
#define SROW 80               // smem row stride (bytes): 32 halves + pad
#define REGN (128 * SROW)     // 10240 bytes per region
#define BUF1 (2 * REGN)       // buffer: A, B

struct GemmCtx {
    uint32_t sbase;
    int warp_m, warp_n, lane;
    uint32_t blane;
    float acc[2][8][4];
};

__device__ __forceinline__ void ctx_init(GemmCtx& g, const void* smem, int tid) {
    g.sbase = smem_u32(smem);
    const int wid = tid >> 5;
    g.lane = tid & 31;
    g.warp_m = wid & 3;
    g.warp_n = wid >> 2;
    g.blane = (uint32_t)(((g.lane & 7) + ((g.lane >> 4) << 3)) * SROW
                         + ((g.lane >> 3) & 1) * 16);
    #pragma unroll
    for (int i = 0; i < 2; i++)
        #pragma unroll
        for (int j = 0; j < 8; j++)
            #pragma unroll
            for (int k = 0; k < 4; k++) g.acc[i][j][k] = 0.f;
}

__device__ __forceinline__ void compute_chunk1(GemmCtx& g, int b) {
    const uint32_t aA = g.sbase + b * BUF1;
    const uint32_t aB = aA + REGN;
    #pragma unroll
    for (int ks = 0; ks < 2; ks++) {
        uint32_t ah[2][4];
        #pragma unroll
        for (int ma = 0; ma < 2; ma++) {
            const uint32_t ao = (uint32_t)((g.warp_m * 32 + ma * 16 + (g.lane & 15)) * SROW
                                           + ks * 32 + (g.lane >> 4) * 16);
            ldm_x4(ah[ma], aA + ao);
        }
        #pragma unroll
        for (int np = 0; np < 4; np++) {
            const uint32_t bo = g.blane + (uint32_t)((g.warp_n * 64 + np * 16) * SROW + ks * 32);
            uint32_t bh[4];
            ldm_x4(bh, aB + bo);
            #pragma unroll
            for (int h = 0; h < 2; h++) {
                const int na = np * 2 + h;
                #pragma unroll
                for (int ma = 0; ma < 2; ma++)
                    mma_fp16(g.acc[ma][na], ah[ma], bh[2 * h], bh[2 * h + 1]);
            }
        }
    }
}

template<typename OutT>
__device__ __forceinline__ void epilogue(GemmCtx& g, const float* bias, OutT* C,
                                         int M, int N, int bm, int bn) {
    #pragma unroll
    for (int ma = 0; ma < 2; ma++) {
        const int row0 = bm + g.warp_m * 32 + ma * 16 + (g.lane >> 2);
        const int row1 = row0 + 8;
        #pragma unroll
        for (int na = 0; na < 8; na++) {
            const int col = bn + g.warp_n * 64 + na * 8 + 2 * (g.lane & 3);
            const float2 bv = *reinterpret_cast<const float2*>(bias + col);
            if constexpr (sizeof(OutT) == 2) {
                if (row0 < M) {
                    __half2 o = __floats2half2_rn(g.acc[ma][na][0] + bv.x, g.acc[ma][na][1] + bv.y);
                    *reinterpret_cast<__half2*>(&C[(size_t)row0 * N + col]) = o;
                }
                if (row1 < M) {
                    __half2 o = __floats2half2_rn(g.acc[ma][na][2] + bv.x, g.acc[ma][na][3] + bv.y);
                    *reinterpret_cast<__half2*>(&C[(size_t)row1 * N + col]) = o;
                }
            } else {
                if (row0 < M) {
                    float2 o = make_float2(g.acc[ma][na][0] + bv.x, g.acc[ma][na][1] + bv.y);
                    *reinterpret_cast<float2*>(&C[(size_t)row0 * N + col]) = o;
                }
                if (row1 < M) {
                    float2 o = make_float2(g.acc[ma][na][2] + bv.x, g.acc[ma][na][3] + bv.y);
                    *reinterpret_cast<float2*>(&C[(size_t)row1 * N + col]) = o;
                }
            }
        }
    }
}

// ---- front GEMM: A fp32 -> fp16 (in-kernel round), B fp16 ------------------
template<typename OutT>
__device__ __forceinline__ void gemm_f32A(
    const float* __restrict__ A,
    const __half* __restrict__ Bh,
    const float* __restrict__ bias,
    OutT* __restrict__ C,
    int M, int N, int bm, int bn)
{
    extern __shared__ uint8_t dyns[];
    const int tid = threadIdx.x;
    GemmCtx g;
    ctx_init(g, dyns, tid);

    const int arow  = tid >> 1;
    const int akseg = (tid & 1) * 16;
    const int gr    = bm + arow;
    const int bn0   = tid >> 2;
    const int bs0   = tid & 3;
    const int bn1   = (256 + tid) >> 2;
    const int bs1   = (256 + tid) & 3;

    float4 f[4];

    auto issue_B = [&](int c, int b) {
        const int k0 = c * 32;
        const uint32_t dB = g.sbase + b * BUF1 + REGN;
        const size_t g0 = (size_t)(bn + bn0) * 256 + k0 + bs0 * 8;
        const size_t g1 = (size_t)(bn + bn1) * 256 + k0 + bs1 * 8;
        cp16(dB + bn0 * SROW + bs0 * 16, Bh + g0);
        cp16(dB + bn1 * SROW + bs1 * 16, Bh + g1);
        CP_COMMIT();
    };
    auto load_A = [&](int c) {
        const int k0 = c * 32;
        if (gr < M) {
            const float4* s = reinterpret_cast<const float4*>(A + (size_t)gr * 256 + k0 + akseg);
            f[0] = s[0]; f[1] = s[1]; f[2] = s[2]; f[3] = s[3];
        } else {
            f[0] = f[1] = f[2] = f[3] = make_float4(0.f, 0.f, 0.f, 0.f);
        }
    };
    auto store_A = [&](int b) {
        uint8_t* sA = dyns + b * BUF1;
        const int aoff = arow * SROW + akseg * 2;
        *reinterpret_cast<uint4*>(sA + aoff) = make_uint4(
            packH(f[0].x, f[0].y), packH(f[0].z, f[0].w),
            packH(f[1].x, f[1].y), packH(f[1].z, f[1].w));
        *reinterpret_cast<uint4*>(sA + aoff + 16) = make_uint4(
            packH(f[2].x, f[2].y), packH(f[2].z, f[2].w),
            packH(f[3].x, f[3].y), packH(f[3].z, f[3].w));
    };

    issue_B(0, 0);
    load_A(0);
    store_A(0);
    CP_WAIT0();
    __syncthreads();

    #pragma unroll 1
    for (int c = 0; c < 8; c++) {
        const int b = c & 1;
        if (c < 7) {
            issue_B(c + 1, b ^ 1);
            load_A(c + 1);
        }
        compute_chunk1(g, b);
        if (c < 7) {
            store_A(b ^ 1);
            CP_WAIT0();
            __syncthreads();
        }
    }
    epilogue(g, bias, C, M, N, bm, bn);
}

// ---- final GEMM: A fp16 (cp.async), B fp16, single pass --------------------
__device__ __forceinline__ void gemm_h16A(
    const __half* __restrict__ Ah,
    const __half* __restrict__ Bh,
    const float* __restrict__ bias,
    float* __restrict__ C,
    int M, int N, int bm, int bn)
{
    extern __shared__ uint8_t dyns[];
    const int tid = threadIdx.x;
    GemmCtx g;
    ctx_init(g, dyns, tid);

    const int r0 = tid >> 2;            // 0..63
    const int s0 = tid & 3;
    const int r1 = (256 + tid) >> 2;    // 64..127
    const int s1 = (256 + tid) & 3;

    auto issue_chunk = [&](int c, int b) {
        const int k0 = c * 32;
        const uint32_t dA = g.sbase + b * BUF1;
        const uint32_t dB = dA + REGN;
        const uint32_t so0 = r0 * SROW + s0 * 16;
        const uint32_t so1 = r1 * SROW + s1 * 16;
        const size_t ga0 = (size_t)(bm + r0) * 256 + k0 + s0 * 8;
        const size_t ga1 = (size_t)(bm + r1) * 256 + k0 + s1 * 8;
        if (bm + r0 < M) cp16(dA + so0, Ah + ga0);
        if (bm + r1 < M) cp16(dA + so1, Ah + ga1);
        const size_t gb0 = (size_t)(bn + r0) * 256 + k0 + s0 * 8;
        const size_t gb1 = (size_t)(bn + r1) * 256 + k0 + s1 * 8;
        cp16(dB + so0, Bh + gb0);
        cp16(dB + so1, Bh + gb1);
        CP_COMMIT();
    };

    issue_chunk(0, 0);
    CP_WAIT0();
    __syncthreads();

    #pragma unroll 1
    for (int c = 0; c < 8; c++) {
        const int b = c & 1;
        if (c < 7) issue_chunk(c + 1, b ^ 1);
        compute_chunk1(g, b);
        if (c < 7) {
            CP_WAIT0();
            __syncthreads();
        }
    }
    epilogue(g, bias, C, M, N, bm, bn);
}

// Fused front GEMMs: grid.x = 5  (0,1: value->fp16 | 2,3: offsets | 4: attn)
__global__ __launch_bounds__(256, 2)
void front_gemm(const float* __restrict__ query,
                const float* __restrict__ inflat,
                const float* __restrict__ b_value,
                const float* __restrict__ b_off,
                const float* __restrict__ b_attn,
                int M)
{
    const int bx = blockIdx.x;
    const int bm = blockIdx.y * 128;
    if (bx < 2) {
        gemm_f32A<__half>(inflat, g_bh, b_value, g_value, M, 256, bm, bx * 128);
    } else if (bx < 4) {
        gemm_f32A<float>(query, g_bh + 65536, b_off, g_off, M, 256, bm, (bx - 2) * 128);
    } else {
        gemm_f32A<float>(query, g_bh + 131072, b_attn, g_attn, M, 128, bm, 0);
    }
}

// Final GEMM: out = head @ w_out + b_out   (A = fp16 sampled head output)
__global__ __launch_bounds__(256, 2)
void final_gemm(const float* __restrict__ b_out, float* __restrict__ out, int M)
{
    gemm_h16A(g_head_h, g_bh + 163840, b_out, out,
              M, 256, blockIdx.y * 128, blockIdx.x * 128);
}

// ---------------- Sampling kernel -----------------------------------------
// One warp per query. lane = head*4 + quad; each lane handles 8 fp16 channels.
// Writes g_head_h (fp16) for the final GEMM.
__device__ __forceinline__ void acc8(float* a, const uint4& v, float w) {
    const __half2* h = reinterpret_cast<const __half2*>(&v);
    #pragma unroll
    for (int i = 0; i < 4; i++) {
        const float2 f = __half22float2(h[i]);
        a[2 * i]     = fmaf(f.x, w, a[2 * i]);
        a[2 * i + 1] = fmaf(f.y, w, a[2 * i + 1]);
    }
}

__global__ __launch_bounds__(256)
void msda_sample(const float* __restrict__ ref)
{
    const int q = blockIdx.x * 8 + (threadIdx.x >> 5);
    if (q >= TOTQ) return;
    const int lane = threadIdx.x & 31;
    const int m = lane >> 2;        // head 0..7
    const int j = lane & 3;         // quad 0..3 (8 channels)
    const int n = (q >= LEN_IN) ? 1 : 0;

    const float4 lg = *reinterpret_cast<const float4*>(&g_attn[(size_t)q * 128 + m * 16 + j * 4]);
    float mx = fmaxf(fmaxf(lg.x, lg.y), fmaxf(lg.z, lg.w));
    mx = fmaxf(mx, __shfl_xor_sync(0xffffffffu, mx, 1, 4));
    mx = fmaxf(mx, __shfl_xor_sync(0xffffffffu, mx, 2, 4));
    const float e0 = __expf(lg.x - mx), e1 = __expf(lg.y - mx);
    const float e2 = __expf(lg.z - mx), e3 = __expf(lg.w - mx);
    float sum = e0 + e1 + e2 + e3;
    sum += __shfl_xor_sync(0xffffffffu, sum, 1, 4);
    sum += __shfl_xor_sync(0xffffffffu, sum, 2, 4);
    const float inv = 1.f / sum;
    const float w0 = e0 * inv, w1 = e1 * inv, w2 = e2 * inv, w3 = e3 * inv;

    const float4 o0 = *reinterpret_cast<const float4*>(&g_off[(size_t)q * 256 + m * 32 + j * 8]);
    const float4 o1 = *reinterpret_cast<const float4*>(&g_off[(size_t)q * 256 + m * 32 + j * 8 + 4]);

    float acc[8];
    #pragma unroll
    for (int i = 0; i < 8; i++) acc[i] = 0.f;

    const __half* vbase = g_value + ((size_t)n * LEN_IN) * 256 + m * 32 + j * 8;

    #pragma unroll
    for (int l = 0; l < N_LEVELS; l++) {
        const int   Wi = c_W[l], Hi = c_H[l];
        const float Wf = (float)Wi, Hf = (float)Hi;
        const float2 r = *reinterpret_cast<const float2*>(&ref[((size_t)q * 4 + l) * 2]);
        const __half* vlev = vbase + (size_t)c_ST[l] * 256;

        #pragma unroll
        for (int p = 0; p < N_POINTS; p++) {
            const int pt = l * 4 + p;          // holder lane = pt>>2, slot = pt&3
            const int sl = pt & 3;
            const float wsel = (sl == 0) ? w0 : (sl == 1) ? w1 : (sl == 2) ? w2 : w3;
            const float oxsel = (sl == 0) ? o0.x : (sl == 1) ? o0.z : (sl == 2) ? o1.x : o1.z;
            const float oysel = (sl == 0) ? o0.y : (sl == 1) ? o0.w : (sl == 2) ? o1.y : o1.w;
            const float w_lp = __shfl_sync(0xffffffffu, wsel, pt >> 2, 4);
            const float ox   = __shfl_sync(0xffffffffu, oxsel, pt >> 2, 4);
            const float oy   = __shfl_sync(0xffffffffu, oysel, pt >> 2, 4);

            const float x = fmaf(r.x, Wf, ox) - 0.5f;
            const float y = fmaf(r.y, Hf, oy) - 0.5f;
            const float x0f = floorf(x);
            const float y0f = floorf(y);
            const float lx = x - x0f;
            const float ly = y - y0f;
            const int x0 = (int)x0f;
            const int y0 = (int)y0f;

            const float fx0 = ((unsigned)x0 < (unsigned)Wi) ? 1.f : 0.f;
            const float fx1 = ((unsigned)(x0 + 1) < (unsigned)Wi) ? 1.f : 0.f;
            const float fy0 = ((unsigned)y0 < (unsigned)Hi) ? 1.f : 0.f;
            const float fy1 = ((unsigned)(y0 + 1) < (unsigned)Hi) ? 1.f : 0.f;
            const int cx0 = min(max(x0, 0), Wi - 1);
            const int cx1 = min(max(x0 + 1, 0), Wi - 1);
            const int cy0 = min(max(y0, 0), Hi - 1);
            const int cy1 = min(max(y0 + 1, 0), Hi - 1);

            const float w00 = (1.f - lx) * (1.f - ly) * w_lp * (fx0 * fy0);
            const float w01 = lx * (1.f - ly) * w_lp * (fx1 * fy0);
            const float w10 = (1.f - lx) * ly * w_lp * (fx0 * fy1);
            const float w11 = lx * ly * w_lp * (fx1 * fy1);

            const __half* r0 = vlev + (size_t)(cy0 * Wi) * 256;
            const __half* r1 = vlev + (size_t)(cy1 * Wi) * 256;
            const uint4 v00 = *reinterpret_cast<const uint4*>(r0 + (size_t)cx0 * 256);
            const uint4 v01 = *reinterpret_cast<const uint4*>(r0 + (size_t)cx1 * 256);
            const uint4 v10 = *reinterpret_cast<const uint4*>(r1 + (size_t)cx0 * 256);
            const uint4 v11 = *reinterpret_cast<const uint4*>(r1 + (size_t)cx1 * 256);

            acc8(acc, v00, w00);
            acc8(acc, v01, w01);
            acc8(acc, v10, w10);
            acc8(acc, v11, w11);
        }
    }

    // write fp16 for the final GEMM's A operand
    const size_t doff = (size_t)q * 256 + m * 32 + j * 8;
    *reinterpret_cast<uint4*>(&g_head_h[doff]) = make_uint4(
        packH(acc[0], acc[1]), packH(acc[2], acc[3]),
        packH(acc[4], acc[5]), packH(acc[6], acc[7]));
}

// ---------------- Launch --------------------------------------------------
extern "C" void kernel_launch(void* const* d_in, const int* in_sizes, int n_in,
                              void* d_out, int out_size)
{
    const float* query   = (const float*)d_in[0];
    const float* refpts  = (const float*)d_in[1];
    const float* inflat  = (const float*)d_in[2];
    const float* w_value = (const float*)d_in[5];
    const float* b_value = (const float*)d_in[6];
    const float* w_off   = (const float*)d_in[7];
    const float* b_off   = (const float*)d_in[8];
    const float* w_attn  = (const float*)d_in[9];
    const float* b_attn  = (const float*)d_in[10];
    const float* w_out   = (const float*)d_in[11];
    const float* b_out   = (const float*)d_in[12];
    float* out = (float*)d_out;

    const int SMEM = 2 * BUF1;   // 40960
    cudaFuncSetAttribute(front_gemm, cudaFuncAttributeMaxDynamicSharedMemorySize, SMEM);
    cudaFuncSetAttribute(final_gemm, cudaFuncAttributeMaxDynamicSharedMemorySize, SMEM);

    const int M = TOTQ;
    const int mblocks = (M + 127) / 128;   // 348

    prep_weights<<<896, 256>>>(w_value, w_off, w_attn, w_out);

    front_gemm<<<dim3(5, mblocks), 256, SMEM>>>(query, inflat, b_value, b_off, b_attn, M);

    const int nblocks = (TOTQ + 7) / 8;
    msda_sample<<<nblocks, 256>>>(refpts);

    final_gemm<<<dim3(2, mblocks), 256, SMEM>>>(b_out, out, M);
}

// round 17
// speedup vs baseline: 1.5270x; 1.0081x over previous
#include <cuda_runtime.h>
#include <cuda_bf16.h>
#include <cuda_fp16.h>
#include <cstdint>

// ---------------- Problem constants (fixed by the dataset) ----------------
#define D_MODEL   256
#define N_HEADS   8
#define HEAD_DIM  32
#define N_LEVELS  4
#define N_POINTS  4
#define LEN_IN    22223
#define NBATCH    2
#define TOTQ      (NBATCH * LEN_IN)   // 44446

__device__ __constant__ int   c_W[4] = {167, 84, 42, 21};
__device__ __constant__ int   c_H[4] = {100, 50, 25, 13};
__device__ __constant__ int   c_ST[4] = {0, 16700, 20900, 21950};

// ---------------- Scratch (device globals; no allocation allowed) ---------
__device__ __half g_value[(size_t)TOTQ * 256];   // fp16 value (written by GEMM)
__device__ float  g_off  [(size_t)TOTQ * 256];
__device__ float  g_attn [(size_t)TOTQ * 128];
__device__ __half g_head_h[(size_t)TOTQ * 256];  // sampled head out, fp16
// fp16 weights, [n][k] row-major (k contiguous, 256 per row)
// [0,65536)=w_value  [65536,131072)=w_off  [131072,163840)=w_attn  [163840,229376)=w_out
__device__ __half g_bh[229376];

// ---------------- helpers ---------------------------------------------------
__device__ __forceinline__ uint32_t smem_u32(const void* p) {
    uint32_t a;
    asm("{ .reg .u64 t; cvta.to.shared.u64 t, %1; cvt.u32.u64 %0, t; }" : "=r"(a) : "l"(p));
    return a;
}
__device__ __forceinline__ uint32_t packH(float a, float b) {
    const __half2 h = __floats2half2_rn(a, b);
    return *reinterpret_cast<const uint32_t*>(&h);
}
__device__ __forceinline__ void ldm_x4(uint32_t* r, uint32_t addr) {
    asm volatile("ldmatrix.sync.aligned.m8n8.x4.shared.b16 {%0,%1,%2,%3}, [%4];"
                 : "=r"(r[0]), "=r"(r[1]), "=r"(r[2]), "=r"(r[3]) : "r"(addr));
}
__device__ __forceinline__ void mma_fp16(float* d, const uint32_t* a, uint32_t b0, uint32_t b1) {
    asm volatile(
        "mma.sync.aligned.m16n8k16.row.col.f32.f16.f16.f32 "
        "{%0,%1,%2,%3}, {%4,%5,%6,%7}, {%8,%9}, {%0,%1,%2,%3};"
        : "+f"(d[0]), "+f"(d[1]), "+f"(d[2]), "+f"(d[3])
        : "r"(a[0]), "r"(a[1]), "r"(a[2]), "r"(a[3]), "r"(b0), "r"(b1));
}
__device__ __forceinline__ void cp16(uint32_t dst, const void* src) {
    asm volatile("cp.async.cg.shared.global [%0], [%1], 16;" :: "r"(dst), "l"(src) : "memory");
}
#define CP_COMMIT() asm volatile("cp.async.commit_group;" ::: "memory")
#define CP_WAIT0()  asm volatile("cp.async.wait_group 0;" ::: "memory")

// ---------------- Weight prep: transpose + fp16 round ----------------------
__global__ void prep_weights(const float* __restrict__ wv, const float* __restrict__ wo,
                             const float* __restrict__ wa, const float* __restrict__ wu)
{
    const int idx = blockIdx.x * 256 + threadIdx.x;
    if (idx >= 229376) return;
    float a;
    if (idx < 65536)       { int l = idx;          int n = l >> 8, k = l & 255; a = wv[k * 256 + n]; }
    else if (idx < 131072) { int l = idx - 65536;  int n = l >> 8, k = l & 255; a = wo[k * 256 + n]; }
    else if (idx < 163840) { int l = idx - 131072; int n = l >> 8, k = l & 255; a = wa[k * 128 + n]; }
    else                   { int l = idx - 163840; int n = l >> 8, k = l & 255; a = wu[k * 256 + n]; }
    g_bh[idx] = __float2half_rn(a);
}

// ---------------- GEMM common ----------------------------------------------
// 128x128 CTA tile, BK=32, 512 threads = 16 warps (4m x 4n), warp tile 32x32.
// Single-pass fp16 (A and B rounded to fp16, fp32 accumulate).
#define SROW 80               // smem row stride (bytes): 32 halves + pad
#define REGN (128 * SROW)     // 10240 bytes per region
#define BUF1 (2 * REGN)       // buffer: A, B

struct GemmCtx {
    uint32_t sbase;
    int warp_m, warp_n, lane;
    uint32_t blane;
    float acc[2][4][4];
};

__device__ __forceinline__ void ctx_init(GemmCtx& g, const void* smem, int tid) {
    g.sbase = smem_u32(smem);
    const int wid = tid >> 5;
    g.lane = tid & 31;
    g.warp_m = wid & 3;       // 0..3 -> 32 rows each
    g.warp_n = wid >> 2;      // 0..3 -> 32 cols each
    g.blane = (uint32_t)(((g.lane & 7) + ((g.lane >> 4) << 3)) * SROW
                         + ((g.lane >> 3) & 1) * 16);
    #pragma unroll
    for (int i = 0; i < 2; i++)
        #pragma unroll
        for (int j = 0; j < 4; j++)
            #pragma unroll
            for (int k = 0; k < 4; k++) g.acc[i][j][k] = 0.f;
}

__device__ __forceinline__ void compute_chunk1(GemmCtx& g, int b) {
    const uint32_t aA = g.sbase + b * BUF1;
    const uint32_t aB = aA + REGN;
    #pragma unroll
    for (int ks = 0; ks < 2; ks++) {
        uint32_t ah[2][4];
        #pragma unroll
        for (int ma = 0; ma < 2; ma++) {
            const uint32_t ao = (uint32_t)((g.warp_m * 32 + ma * 16 + (g.lane & 15)) * SROW
                                           + ks * 32 + (g.lane >> 4) * 16);
            ldm_x4(ah[ma], aA + ao);
        }
        #pragma unroll
        for (int np = 0; np < 2; np++) {
            const uint32_t bo = g.blane + (uint32_t)((g.warp_n * 32 + np * 16) * SROW + ks * 32);
            uint32_t bh[4];
            ldm_x4(bh, aB + bo);
            #pragma unroll
            for (int h = 0; h < 2; h++) {
                const int na = np * 2 + h;
                #pragma unroll
                for (int ma = 0; ma < 2; ma++)
                    mma_fp16(g.acc[ma][na], ah[ma], bh[2 * h], bh[2 * h + 1]);
            }
        }
    }
}

template<typename OutT>
__device__ __forceinline__ void epilogue(GemmCtx& g, const float* bias, OutT* C,
                                         int M, int N, int bm, int bn) {
    #pragma unroll
    for (int ma = 0; ma < 2; ma++) {
        const int row0 = bm + g.warp_m * 32 + ma * 16 + (g.lane >> 2);
        const int row1 = row0 + 8;
        #pragma unroll
        for (int na = 0; na < 4; na++) {
            const int col = bn + g.warp_n * 32 + na * 8 + 2 * (g.lane & 3);
            const float2 bv = *reinterpret_cast<const float2*>(bias + col);
            if constexpr (sizeof(OutT) == 2) {
                if (row0 < M) {
                    __half2 o = __floats2half2_rn(g.acc[ma][na][0] + bv.x, g.acc[ma][na][1] + bv.y);
                    *reinterpret_cast<__half2*>(&C[(size_t)row0 * N + col]) = o;
                }
                if (row1 < M) {
                    __half2 o = __floats2half2_rn(g.acc[ma][na][2] + bv.x, g.acc[ma][na][3] + bv.y);
                    *reinterpret_cast<__half2*>(&C[(size_t)row1 * N + col]) = o;
                }
            } else {
                if (row0 < M) {
                    float2 o = make_float2(g.acc[ma][na][0] + bv.x, g.acc[ma][na][1] + bv.y);
                    *reinterpret_cast<float2*>(&C[(size_t)row0 * N + col]) = o;
                }
                if (row1 < M) {
                    float2 o = make_float2(g.acc[ma][na][2] + bv.x, g.acc[ma][na][3] + bv.y);
                    *reinterpret_cast<float2*>(&C[(size_t)row1 * N + col]) = o;
                }
            }
        }
    }
}

// ---- front GEMM: A fp32 -> fp16 (in-kernel round), B fp16 ------------------
template<typename OutT>
__device__ __forceinline__ void gemm_f32A(
    const float* __restrict__ A,
    const __half* __restrict__ Bh,
    const float* __restrict__ bias,
    OutT* __restrict__ C,
    int M, int N, int bm, int bn)
{
    extern __shared__ uint8_t dyns[];
    const int tid = threadIdx.x;
    GemmCtx g;
    ctx_init(g, dyns, tid);

    // A: 128 rows x 32 fp32 per chunk; 4 threads/row, 2 float4 each
    const int arow = tid >> 2;           // 0..127
    const int asg  = tid & 3;            // float4 groups asg and asg+4
    const int gr   = bm + arow;
    // B: 128 rows x 32 fp16 = 512 x 16B; 1 per thread
    const int bnr  = tid >> 2;
    const int bsg  = tid & 3;

    float4 f0, f1;

    auto issue_B = [&](int c, int b) {
        const int k0 = c * 32;
        const uint32_t dB = g.sbase + b * BUF1 + REGN;
        const size_t go = (size_t)(bn + bnr) * 256 + k0 + bsg * 8;
        cp16(dB + bnr * SROW + bsg * 16, Bh + go);
        CP_COMMIT();
    };
    auto load_A = [&](int c) {
        const int k0 = c * 32;
        if (gr < M) {
            const float4* s = reinterpret_cast<const float4*>(A + (size_t)gr * 256 + k0);
            f0 = s[asg];
            f1 = s[asg + 4];
        } else {
            f0 = f1 = make_float4(0.f, 0.f, 0.f, 0.f);
        }
    };
    auto store_A = [&](int b) {
        uint8_t* sA = dyns + b * BUF1;
        const int base = arow * SROW;
        *reinterpret_cast<uint2*>(sA + base + asg * 8) =
            make_uint2(packH(f0.x, f0.y), packH(f0.z, f0.w));
        *reinterpret_cast<uint2*>(sA + base + (asg + 4) * 8) =
            make_uint2(packH(f1.x, f1.y), packH(f1.z, f1.w));
    };

    issue_B(0, 0);
    load_A(0);
    store_A(0);
    CP_WAIT0();
    __syncthreads();

    #pragma unroll 1
    for (int c = 0; c < 8; c++) {
        const int b = c & 1;
        if (c < 7) {
            issue_B(c + 1, b ^ 1);
            load_A(c + 1);
        }
        compute_chunk1(g, b);
        if (c < 7) {
            store_A(b ^ 1);
            CP_WAIT0();
            __syncthreads();
        }
    }
    epilogue(g, bias, C, M, N, bm, bn);
}

// ---- final GEMM: A fp16 (cp.async), B fp16, single pass --------------------
__device__ __forceinline__ void gemm_h16A(
    const __half* __restrict__ Ah,
    const __half* __restrict__ Bh,
    const float* __restrict__ bias,
    float* __restrict__ C,
    int M, int N, int bm, int bn)
{
    extern __shared__ uint8_t dyns[];
    const int tid = threadIdx.x;
    GemmCtx g;
    ctx_init(g, dyns, tid);

    const int r0 = tid >> 2;     // 0..127
    const int s0 = tid & 3;

    auto issue_chunk = [&](int c, int b) {
        const int k0 = c * 32;
        const uint32_t dA = g.sbase + b * BUF1;
        const uint32_t dB = dA + REGN;
        const uint32_t so = r0 * SROW + s0 * 16;
        const size_t ga = (size_t)(bm + r0) * 256 + k0 + s0 * 8;
        if (bm + r0 < M) cp16(dA + so, Ah + ga);
        const size_t gb = (size_t)(bn + r0) * 256 + k0 + s0 * 8;
        cp16(dB + so, Bh + gb);
        CP_COMMIT();
    };

    issue_chunk(0, 0);
    CP_WAIT0();
    __syncthreads();

    #pragma unroll 1
    for (int c = 0; c < 8; c++) {
        const int b = c & 1;
        if (c < 7) issue_chunk(c + 1, b ^ 1);
        compute_chunk1(g, b);
        if (c < 7) {
            CP_WAIT0();
            __syncthreads();
        }
    }
    epilogue(g, bias, C, M, N, bm, bn);
}

// Fused front GEMMs: grid.x = 5  (0,1: value->fp16 | 2,3: offsets | 4: attn)
__global__ __launch_bounds__(512, 2)
void front_gemm(const float* __restrict__ query,
                const float* __restrict__ inflat,
                const float* __restrict__ b_value,
                const float* __restrict__ b_off,
                const float* __restrict__ b_attn,
                int M)
{
    const int bx = blockIdx.x;
    const int bm = blockIdx.y * 128;
    if (bx < 2) {
        gemm_f32A<__half>(inflat, g_bh, b_value, g_value, M, 256, bm, bx * 128);
    } else if (bx < 4) {
        gemm_f32A<float>(query, g_bh + 65536, b_off, g_off, M, 256, bm, (bx - 2) * 128);
    } else {
        gemm_f32A<float>(query, g_bh + 131072, b_attn, g_attn, M, 128, bm, 0);
    }
}

// Final GEMM: out = head @ w_out + b_out   (A = fp16 sampled head output)
__global__ __launch_bounds__(512, 2)
void final_gemm(const float* __restrict__ b_out, float* __restrict__ out, int M)
{
    gemm_h16A(g_head_h, g_bh + 163840, b_out, out,
              M, 256, blockIdx.y * 128, blockIdx.x * 128);
}

// ---------------- Sampling kernel -----------------------------------------
// One warp per query. lane = head*4 + quad; each lane handles 8 fp16 channels.
// Writes g_head_h (fp16) for the final GEMM.
__device__ __forceinline__ void acc8(float* a, const uint4& v, float w) {
    const __half2* h = reinterpret_cast<const __half2*>(&v);
    #pragma unroll
    for (int i = 0; i < 4; i++) {
        const float2 f = __half22float2(h[i]);
        a[2 * i]     = fmaf(f.x, w, a[2 * i]);
        a[2 * i + 1] = fmaf(f.y, w, a[2 * i + 1]);
    }
}

__global__ __launch_bounds__(256)
void msda_sample(const float* __restrict__ ref)
{
    const int q = blockIdx.x * 8 + (threadIdx.x >> 5);
    if (q >= TOTQ) return;
    const int lane = threadIdx.x & 31;
    const int m = lane >> 2;        // head 0..7
    const int j = lane & 3;         // quad 0..3 (8 channels)
    const int n = (q >= LEN_IN) ? 1 : 0;

    const float4 lg = *reinterpret_cast<const float4*>(&g_attn[(size_t)q * 128 + m * 16 + j * 4]);
    float mx = fmaxf(fmaxf(lg.x, lg.y), fmaxf(lg.z, lg.w));
    mx = fmaxf(mx, __shfl_xor_sync(0xffffffffu, mx, 1, 4));
    mx = fmaxf(mx, __shfl_xor_sync(0xffffffffu, mx, 2, 4));
    const float e0 = __expf(lg.x - mx), e1 = __expf(lg.y - mx);
    const float e2 = __expf(lg.z - mx), e3 = __expf(lg.w - mx);
    float sum = e0 + e1 + e2 + e3;
    sum += __shfl_xor_sync(0xffffffffu, sum, 1, 4);
    sum += __shfl_xor_sync(0xffffffffu, sum, 2, 4);
    const float inv = 1.f / sum;
    const float w0 = e0 * inv, w1 = e1 * inv, w2 = e2 * inv, w3 = e3 * inv;

    const float4 o0 = *reinterpret_cast<const float4*>(&g_off[(size_t)q * 256 + m * 32 + j * 8]);
    const float4 o1 = *reinterpret_cast<const float4*>(&g_off[(size_t)q * 256 + m * 32 + j * 8 + 4]);

    float acc[8];
    #pragma unroll
    for (int i = 0; i < 8; i++) acc[i] = 0.f;

    const __half* vbase = g_value + ((size_t)n * LEN_IN) * 256 + m * 32 + j * 8;

    #pragma unroll
    for (int l = 0; l < N_LEVELS; l++) {
        const int   Wi = c_W[l], Hi = c_H[l];
        const float Wf = (float)Wi, Hf = (float)Hi;
        const float2 r = *reinterpret_cast<const float2*>(&ref[((size_t)q * 4 + l) * 2]);
        const __half* vlev = vbase + (size_t)c_ST[l] * 256;

        #pragma unroll
        for (int p = 0; p < N_POINTS; p++) {
            const int pt = l * 4 + p;          // holder lane = pt>>2, slot = pt&3
            const int sl = pt & 3;
            const float wsel = (sl == 0) ? w0 : (sl == 1) ? w1 : (sl == 2) ? w2 : w3;
            const float oxsel = (sl == 0) ? o0.x : (sl == 1) ? o0.z : (sl == 2) ? o1.x : o1.z;
            const float oysel = (sl == 0) ? o0.y : (sl == 1) ? o0.w : (sl == 2) ? o1.y : o1.w;
            const float w_lp = __shfl_sync(0xffffffffu, wsel, pt >> 2, 4);
            const float ox   = __shfl_sync(0xffffffffu, oxsel, pt >> 2, 4);
            const float oy   = __shfl_sync(0xffffffffu, oysel, pt >> 2, 4);

            const float x = fmaf(r.x, Wf, ox) - 0.5f;
            const float y = fmaf(r.y, Hf, oy) - 0.5f;
            const float x0f = floorf(x);
            const float y0f = floorf(y);
            const float lx = x - x0f;
            const float ly = y - y0f;
            const int x0 = (int)x0f;
            const int y0 = (int)y0f;

            const float fx0 = ((unsigned)x0 < (unsigned)Wi) ? 1.f : 0.f;
            const float fx1 = ((unsigned)(x0 + 1) < (unsigned)Wi) ? 1.f : 0.f;
            const float fy0 = ((unsigned)y0 < (unsigned)Hi) ? 1.f : 0.f;
            const float fy1 = ((unsigned)(y0 + 1) < (unsigned)Hi) ? 1.f : 0.f;
            const int cx0 = min(max(x0, 0), Wi - 1);
            const int cx1 = min(max(x0 + 1, 0), Wi - 1);
            const int cy0 = min(max(y0, 0), Hi - 1);
            const int cy1 = min(max(y0 + 1, 0), Hi - 1);

            const float w00 = (1.f - lx) * (1.f - ly) * w_lp * (fx0 * fy0);
            const float w01 = lx * (1.f - ly) * w_lp * (fx1 * fy0);
            const float w10 = (1.f - lx) * ly * w_lp * (fx0 * fy1);
            const float w11 = lx * ly * w_lp * (fx1 * fy1);

            const __half* r0 = vlev + (size_t)(cy0 * Wi) * 256;
            const __half* r1 = vlev + (size_t)(cy1 * Wi) * 256;
            const uint4 v00 = *reinterpret_cast<const uint4*>(r0 + (size_t)cx0 * 256);
            const uint4 v01 = *reinterpret_cast<const uint4*>(r0 + (size_t)cx1 * 256);
            const uint4 v10 = *reinterpret_cast<const uint4*>(r1 + (size_t)cx0 * 256);
            const uint4 v11 = *reinterpret_cast<const uint4*>(r1 + (size_t)cx1 * 256);

            acc8(acc, v00, w00);
            acc8(acc, v01, w01);
            acc8(acc, v10, w10);
            acc8(acc, v11, w11);
        }
    }

    // write fp16 for the final GEMM's A operand
    const size_t doff = (size_t)q * 256 + m * 32 + j * 8;
    *reinterpret_cast<uint4*>(&g_head_h[doff]) = make_uint4(
        packH(acc[0], acc[1]), packH(acc[2], acc[3]),
        packH(acc[4], acc[5]), packH(acc[6], acc[7]));
}

// ---------------- Launch --------------------------------------------------
extern "C" void kernel_launch(void* const* d_in, const int* in_sizes, int n_in,
                              void* d_out, int out_size)
{
    const float* query   = (const float*)d_in[0];
    const float* refpts  = (const float*)d_in[1];
    const float* inflat  = (const float*)d_in[2];
    const float* w_value = (const float*)d_in[5];
    const float* b_value = (const float*)d_in[6];
    const float* w_off   = (const float*)d_in[7];
    const float* b_off   = (const float*)d_in[8];
    const float* w_attn  = (const float*)d_in[9];
    const float* b_attn  = (const float*)d_in[10];
    const float* w_out   = (const float*)d_in[11];
    const float* b_out   = (const float*)d_in[12];
    float* out = (float*)d_out;

    const int SMEM = 2 * BUF1;   // 40960
    cudaFuncSetAttribute(front_gemm, cudaFuncAttributeMaxDynamicSharedMemorySize, SMEM);
    cudaFuncSetAttribute(final_gemm, cudaFuncAttributeMaxDynamicSharedMemorySize, SMEM);

    const int M = TOTQ;
    const int mblocks = (M + 127) / 128;   // 348

    prep_weights<<<896, 256>>>(w_value, w_off, w_attn, w_out);

    front_gemm<<<dim3(5, mblocks), 512, SMEM>>>(query, inflat, b_value, b_off, b_attn, M);

    const int nblocks = (TOTQ + 7) / 8;
    msda_sample<<<nblocks, 256>>>(refpts);

    final_gemm<<<dim3(2, mblocks), 512, SMEM>>>(b_out, out, M);
}